// round 1
// baseline (speedup 1.0000x reference)
#include <cuda_runtime.h>

// Problem constants (shapes fixed for this problem instance)
#define B_    4
#define T_    1024
#define C_    512
#define V_    4096
#define H_    8
#define D_    64
#define Q_    256
#define MFULL 4096   // B*T rows
#define MREST 1024   // B*Q rows
#define MTOT  5120
#define ZHAT_ELEMS (B_*C_*T_)

// 1/sqrt(D)/sqrt(H) = 1/8 * 1/sqrt(8)
#define COMB_SCALE 0.044194173824159216f

// ---- scratch (device globals; no allocation allowed) ----
__device__ float g_hs[MFULL*C_];      // z transposed: (b,t,c)
__device__ float g_Xq[MFULL*C_];      // hs@Wq + bq (raw, pre-rmsnorm)
__device__ float g_Xp[MFULL*H_];      // hs@Wp + bp
__device__ float g_value[V_*C_];      // codebook@Wv + bv
__device__ float g_kh[V_*C_];         // codebook@Wk + bk, then rmsnorm*gk in place
__device__ float g_Q[MTOT*C_];        // combined query vectors (full rows 0..4095, rest 4096..5119)
__device__ unsigned long long g_keys[MTOT];
__device__ int g_cnt[V_];

// ---------------------------------------------------------------------------
// transpose z (B,C,T) -> hs (B*T, C)
__global__ void k_transpose(const float* __restrict__ z) {
    __shared__ float tile[32][33];
    int b  = blockIdx.z;
    int c0 = blockIdx.x << 5;
    int t0 = blockIdx.y << 5;
    int tx = threadIdx.x, ty = threadIdx.y;
#pragma unroll
    for (int j = 0; j < 4; j++)
        tile[ty + 8*j][tx] = z[(b*C_ + c0 + ty + 8*j)*T_ + t0 + tx];
    __syncthreads();
#pragma unroll
    for (int j = 0; j < 4; j++)
        g_hs[(b*T_ + t0 + ty + 8*j)*C_ + c0 + tx] = tile[tx][ty + 8*j];
}

// ---------------------------------------------------------------------------
// C[M x N] = A[M x 512] @ B[512 x N] + bias.  BM=128, BN=64, BK=16, 256 thr, 8x4/thr
__global__ void k_gemm512(const float* __restrict__ A, const float* __restrict__ Bm,
                          const float* __restrict__ bias, float* __restrict__ C, int N) {
    __shared__ float As[16][128];
    __shared__ float Bs[16][64];
    int tid = threadIdx.x;
    int tx = tid & 15, ty = tid >> 4;
    int m0 = blockIdx.y << 7, n0 = blockIdx.x << 6;
    int ar = tid >> 2, ac = (tid & 3) << 2;
    int br = tid >> 4, bc = (tid & 15) << 2;
    float acc[8][4] = {};
    for (int k0 = 0; k0 < 512; k0 += 16) {
        float4 a0 = *(const float4*)(A + (size_t)(m0 + ar)      * 512 + k0 + ac);
        float4 a1 = *(const float4*)(A + (size_t)(m0 + ar + 64) * 512 + k0 + ac);
        float4 b0 = *(const float4*)(Bm + (size_t)(k0 + br) * N + n0 + bc);
        As[ac+0][ar] = a0.x; As[ac+1][ar] = a0.y; As[ac+2][ar] = a0.z; As[ac+3][ar] = a0.w;
        As[ac+0][ar+64] = a1.x; As[ac+1][ar+64] = a1.y; As[ac+2][ar+64] = a1.z; As[ac+3][ar+64] = a1.w;
        *(float4*)(&Bs[br][bc]) = b0;
        __syncthreads();
#pragma unroll
        for (int k = 0; k < 16; k++) {
            float a[8], bb[4];
            *(float4*)(a)     = *(const float4*)(&As[k][ty*8]);
            *(float4*)(a + 4) = *(const float4*)(&As[k][ty*8 + 4]);
            *(float4*)(bb)    = *(const float4*)(&Bs[k][tx*4]);
#pragma unroll
            for (int i = 0; i < 8; i++)
#pragma unroll
                for (int j = 0; j < 4; j++)
                    acc[i][j] += a[i] * bb[j];
        }
        __syncthreads();
    }
#pragma unroll
    for (int i = 0; i < 8; i++)
#pragma unroll
        for (int j = 0; j < 4; j++) {
            int r = m0 + ty*8 + i, c = n0 + tx*4 + j;
            C[(size_t)r * N + c] = acc[i][j] + bias[c];
        }
}

// ---------------------------------------------------------------------------
// Xp = hs @ Wp + bp   (512 -> 8)
__global__ void k_xp(const float* __restrict__ Wp, const float* __restrict__ bp) {
    int idx = blockIdx.x * blockDim.x + threadIdx.x;
    if (idx >= MFULL * H_) return;
    int row = idx >> 3, h = idx & 7;
    const float* hsr = g_hs + (size_t)row * C_;
    float s = bp[h];
#pragma unroll 8
    for (int k = 0; k < C_; k++) s += hsr[k] * Wp[k*H_ + h];
    g_Xp[idx] = s;
}

// ---------------------------------------------------------------------------
// rmsnorm helpers: block = 512 threads = one row; reduce x*x per 64-chunk (head)
__device__ __forceinline__ float head_rms_scale(float x, int d, float* ws) {
    float s = x * x;
#pragma unroll
    for (int o = 16; o; o >>= 1) s += __shfl_xor_sync(0xffffffffu, s, o);
    if ((d & 31) == 0) ws[d >> 5] = s;
    __syncthreads();
    int h = d >> 6;
    float tot = ws[2*h] + ws[2*h + 1];
    return rsqrtf(tot * (1.0f/64.0f) + 1e-5f);
}

__global__ void k_khnorm(const float* __restrict__ gk) {
    __shared__ float ws[16];
    int row = blockIdx.x, d = threadIdx.x;
    float x = g_kh[(size_t)row*C_ + d];
    float r = head_rms_scale(x, d, ws);
    g_kh[(size_t)row*C_ + d] = x * r * gk[d & 63];
}

__global__ void k_qfull(const float* __restrict__ gq) {
    __shared__ float ws[16];
    int row = blockIdx.x, d = threadIdx.x, h = d >> 6;
    float x = g_Xq[(size_t)row*C_ + d];
    float r = head_rms_scale(x, d, ws);
    float c = g_Xp[row*H_ + h];
    g_Q[(size_t)row*C_ + d] = x * r * gq[d & 63] * c * COMB_SCALE;
}

__global__ void k_qrest(const float* __restrict__ gq) {
    __shared__ float ws[16];
    int row = blockIdx.x, d = threadIdx.x, h = d >> 6;   // row = b*256 + i
    int fr = (row >> 8) * T_ + (row & 255) * 4;          // first full-res row of window
    const float* p = g_Xq + (size_t)fr*C_ + d;
    float x = 0.25f * (p[0] + p[C_] + p[2*C_] + p[3*C_]);
    float r = head_rms_scale(x, d, ws);
    const float* pc = g_Xp + fr*H_ + h;
    float c = 0.25f * (pc[0] + pc[H_] + pc[2*H_] + pc[3*H_]);
    g_Q[(size_t)(MFULL + row)*C_ + d] = x * r * gq[d & 63] * c * COMB_SCALE;
}

// ---------------------------------------------------------------------------
__global__ void k_init() {
    int i = blockIdx.x * blockDim.x + threadIdx.x;
    if (i < MTOT) g_keys[i] = 0ull;
    if (i < V_)   g_cnt[i]  = 0;
}

__device__ __forceinline__ unsigned fkey(float f) {
    unsigned u = __float_as_uint(f);
    return (u & 0x80000000u) ? ~u : (u | 0x80000000u);
}

// argmax_n dot(Q[m,:], kh[n,:]) -> g_keys[m].  NT gemm, fused argmax epilogue.
// BM=128, BN=64, BK=16, 256 thr. grid = (64 n-tiles, 40 m-tiles)
__global__ void k_argmax(const float* __restrict__ Aq) {
    __shared__ float As[16][128];
    __shared__ float Bs[16][64];
    __shared__ unsigned long long red[128][16];
    int tid = threadIdx.x;
    int tx = tid & 15, ty = tid >> 4;
    int m0 = blockIdx.y << 7, n0 = blockIdx.x << 6;
    int ar = tid >> 2, ac = (tid & 3) << 2;   // also n-row / k-col for B tile
    float acc[8][4] = {};
    for (int k0 = 0; k0 < 512; k0 += 16) {
        float4 a0 = *(const float4*)(Aq  + (size_t)(m0 + ar)      * 512 + k0 + ac);
        float4 a1 = *(const float4*)(Aq  + (size_t)(m0 + ar + 64) * 512 + k0 + ac);
        float4 b0 = *(const float4*)(g_kh + (size_t)(n0 + ar) * 512 + k0 + ac);
        As[ac+0][ar] = a0.x; As[ac+1][ar] = a0.y; As[ac+2][ar] = a0.z; As[ac+3][ar] = a0.w;
        As[ac+0][ar+64] = a1.x; As[ac+1][ar+64] = a1.y; As[ac+2][ar+64] = a1.z; As[ac+3][ar+64] = a1.w;
        Bs[ac+0][ar & 63] = b0.x; Bs[ac+1][ar & 63] = b0.y; Bs[ac+2][ar & 63] = b0.z; Bs[ac+3][ar & 63] = b0.w;
        __syncthreads();
#pragma unroll
        for (int k = 0; k < 16; k++) {
            float a[8], bb[4];
            *(float4*)(a)     = *(const float4*)(&As[k][ty*8]);
            *(float4*)(a + 4) = *(const float4*)(&As[k][ty*8 + 4]);
            *(float4*)(bb)    = *(const float4*)(&Bs[k][tx*4]);
#pragma unroll
            for (int i = 0; i < 8; i++)
#pragma unroll
                for (int j = 0; j < 4; j++)
                    acc[i][j] += a[i] * bb[j];
        }
        __syncthreads();
    }
    // wait: B tile needs rows n0..n0+63 only; threads with ar>=64 duplicate rows.
    // (handled above by ar&63 -- dupes write identical data, benign)
#pragma unroll
    for (int i = 0; i < 8; i++) {
        unsigned long long best = 0ull;
#pragma unroll
        for (int j = 0; j < 4; j++) {
            int n = n0 + tx*4 + j;
            unsigned long long key =
                ((unsigned long long)fkey(acc[i][j]) << 32) | (unsigned)(4095 - n);
            if (key > best) best = key;
        }
        red[ty*8 + i][tx] = best;
    }
    __syncthreads();
    if (tid < 128) {
        unsigned long long b = red[tid][0];
#pragma unroll
        for (int t = 1; t < 16; t++) if (red[tid][t] > b) b = red[tid][t];
        atomicMax(&g_keys[m0 + tid], b);
    }
}

// ---------------------------------------------------------------------------
__global__ void k_hist() {
    int i = blockIdx.x * blockDim.x + threadIdx.x;
    if (i < MFULL) {
        int n = 4095 - (int)(unsigned)(g_keys[i] & 0xFFFFFFFFull);
        atomicAdd(&g_cnt[n], 1);
    }
}

// z_hat gather + linear interp q=256 -> T=1024
__global__ void k_out(float* __restrict__ out) {
    int idx = blockIdx.x * blockDim.x + threadIdx.x;
    if (idx >= ZHAT_ELEMS) return;
    int t = idx & (T_ - 1);
    int d = (idx >> 10) & 511;
    int b = idx >> 19;
    float pos = (t + 0.5f) * ((float)Q_ / (float)T_) - 0.5f;
    pos = fminf(fmaxf(pos, 0.0f), (float)(Q_ - 1));
    int i0 = (int)pos;                 // pos >= 0, trunc == floor
    int i1 = min(i0 + 1, Q_ - 1);
    float w = pos - (float)i0;
    int n0 = 4095 - (int)(unsigned)(g_keys[MFULL + b*Q_ + i0] & 0xFFFFFFFFull);
    int n1 = 4095 - (int)(unsigned)(g_keys[MFULL + b*Q_ + i1] & 0xFFFFFFFFull);
    out[idx] = (1.0f - w) * g_value[(size_t)n0*C_ + d] + w * g_value[(size_t)n1*C_ + d];
}

__global__ void k_perp(float* __restrict__ out) {
    __shared__ float sm[1024];
    int tid = threadIdx.x;
    float s = 0.0f;
    for (int j = tid; j < V_; j += 1024) {
        float p = (float)g_cnt[j] * (1.0f / 4096.0f);
        s += p * logf(p + 1e-7f);
    }
    sm[tid] = s;
    __syncthreads();
    for (int o = 512; o; o >>= 1) {
        if (tid < o) sm[tid] += sm[tid + o];
        __syncthreads();
    }
    if (tid == 0) out[ZHAT_ELEMS] = expf(-sm[0]);
}

// ---------------------------------------------------------------------------
extern "C" void kernel_launch(void* const* d_in, const int* in_sizes, int n_in,
                              void* d_out, int out_size) {
    const float* z        = (const float*)d_in[0];
    // d_in[1] is q (int scalar) = 256, compile-time constant here
    const float* codebook = (const float*)d_in[2];
    const float* Wq = (const float*)d_in[3];
    const float* bq = (const float*)d_in[4];
    const float* Wk = (const float*)d_in[5];
    const float* bk = (const float*)d_in[6];
    const float* Wv = (const float*)d_in[7];
    const float* bv = (const float*)d_in[8];
    const float* Wp = (const float*)d_in[9];
    const float* bp = (const float*)d_in[10];
    const float* gq = (const float*)d_in[11];
    const float* gk = (const float*)d_in[12];
    float* out = (float*)d_out;

    float *p_hs, *p_Xq, *p_val, *p_kh, *p_Q;
    cudaGetSymbolAddress((void**)&p_hs,  g_hs);
    cudaGetSymbolAddress((void**)&p_Xq,  g_Xq);
    cudaGetSymbolAddress((void**)&p_val, g_value);
    cudaGetSymbolAddress((void**)&p_kh,  g_kh);
    cudaGetSymbolAddress((void**)&p_Q,   g_Q);

    k_transpose<<<dim3(16, 32, 4), dim3(32, 8)>>>(z);

    // projections (M=4096, K=512): grid (N/64, M/128)
    k_gemm512<<<dim3(8, 32), 256>>>(p_hs,     Wq, bq, p_Xq,  512);
    k_gemm512<<<dim3(8, 32), 256>>>(codebook, Wk, bk, p_kh,  512);
    k_gemm512<<<dim3(8, 32), 256>>>(codebook, Wv, bv, p_val, 512);
    k_xp<<<(MFULL*H_ + 255)/256, 256>>>(Wp, bp);

    k_khnorm<<<V_,    512>>>(gk);
    k_qfull <<<MFULL, 512>>>(gq);
    k_qrest <<<MREST, 512>>>(gq);

    k_init<<<(MTOT + 255)/256, 256>>>();
    k_argmax<<<dim3(64, 40), 256>>>(p_Q);

    k_hist<<<16, 256>>>();
    k_out<<<(ZHAT_ELEMS + 255)/256, 256>>>(out);
    k_perp<<<1, 1024>>>(out);
}

// round 2
// speedup vs baseline: 1.1245x; 1.1245x over previous
#include <cuda_runtime.h>

// Problem constants (shapes fixed for this problem instance)
#define B_    4
#define T_    1024
#define C_    512
#define V_    4096
#define H_    8
#define D_    64
#define Q_    256
#define MFULL 4096   // B*T rows
#define MREST 1024   // B*Q rows
#define MTOT  5120
#define ZHAT_ELEMS (B_*C_*T_)

// 1/sqrt(D)/sqrt(H)
#define COMB_SCALE 0.044194173824159216f

// ---- scratch (device globals; no allocation allowed) ----
__device__ float g_hs[MFULL*C_];      // z transposed: (b,t,c)
__device__ float g_Xq[MFULL*C_];      // hs@Wq + bq (raw, pre-rmsnorm)
__device__ float g_Xp[MFULL*H_];      // hs@Wp + bp
__device__ float g_value[V_*C_];      // codebook@Wv + bv
__device__ float g_kh[V_*C_];         // codebook@Wk + bk, then rmsnorm*gk in place
__device__ float g_Q[MTOT*C_];        // combined query vectors
__device__ unsigned long long g_keys[MTOT];
__device__ int g_cnt[V_];

// ---------------------------------------------------------------------------
// transpose z (B,C,T) -> hs (B*T, C)
__global__ void k_transpose(const float* __restrict__ z) {
    __shared__ float tile[32][33];
    int b  = blockIdx.z;
    int c0 = blockIdx.x << 5;
    int t0 = blockIdx.y << 5;
    int tx = threadIdx.x, ty = threadIdx.y;
#pragma unroll
    for (int j = 0; j < 4; j++)
        tile[ty + 8*j][tx] = z[(b*C_ + c0 + ty + 8*j)*T_ + t0 + tx];
    __syncthreads();
#pragma unroll
    for (int j = 0; j < 4; j++)
        g_hs[(b*T_ + t0 + ty + 8*j)*C_ + c0 + tx] = tile[tx][ty + 8*j];
}

// ---------------------------------------------------------------------------
// Batched projection GEMM: C = A[4096x512] @ B[512x512] + bias
// BM=BN=128, BK=16, 256 threads, 8x8 per thread, double-buffered smem.
// blockIdx.z: 0 -> hs@Wq->Xq, 1 -> cb@Wk->kh, 2 -> cb@Wv->value
__global__ __launch_bounds__(256, 2) void k_proj(
    const float* __restrict__ cb,
    const float* __restrict__ Wq, const float* __restrict__ bq,
    const float* __restrict__ Wk, const float* __restrict__ bk,
    const float* __restrict__ Wv, const float* __restrict__ bv) {
    __shared__ float As[2][16][132];
    __shared__ float Bs[2][16][132];

    const float *A, *Bm, *bias;
    float* C;
    int zid = blockIdx.z;
    if (zid == 0)      { A = g_hs; Bm = Wq; bias = bq; C = g_Xq; }
    else if (zid == 1) { A = cb;   Bm = Wk; bias = bk; C = g_kh; }
    else               { A = cb;   Bm = Wv; bias = bv; C = g_value; }

    int tid = threadIdx.x;
    int tm = tid >> 4, tn = tid & 15;
    int m0 = blockIdx.y << 7, n0 = blockIdx.x << 7;
    int ar = tid >> 2, ac = (tid & 3) << 2;   // A tile: row ar(+64), k-cols ac..ac+3
    int br = tid >> 4, bc = (tid & 15) << 3;  // B tile: k-row br, n-cols bc..bc+7

    const float* Ap = A  + (size_t)(m0 + ar) * C_ + ac;
    const float* Bp = Bm + (size_t)br * C_ + n0 + bc;

    float4 ra0 = *(const float4*)Ap;
    float4 ra1 = *(const float4*)(Ap + 64 * C_);
    float4 rb0 = *(const float4*)Bp;
    float4 rb1 = *(const float4*)(Bp + 4);

    As[0][ac+0][ar] = ra0.x; As[0][ac+1][ar] = ra0.y;
    As[0][ac+2][ar] = ra0.z; As[0][ac+3][ar] = ra0.w;
    As[0][ac+0][ar+64] = ra1.x; As[0][ac+1][ar+64] = ra1.y;
    As[0][ac+2][ar+64] = ra1.z; As[0][ac+3][ar+64] = ra1.w;
    *(float4*)(&Bs[0][br][bc])   = rb0;
    *(float4*)(&Bs[0][br][bc+4]) = rb1;
    __syncthreads();

    float acc[8][8] = {};
    for (int t = 0; t < 32; ++t) {
        int cur = t & 1;
        if (t < 31) {
            Ap += 16; Bp += 16 * C_;
            ra0 = *(const float4*)Ap;
            ra1 = *(const float4*)(Ap + 64 * C_);
            rb0 = *(const float4*)Bp;
            rb1 = *(const float4*)(Bp + 4);
        }
#pragma unroll
        for (int k = 0; k < 16; ++k) {
            float a[8], b[8];
            *(float4*)(a)     = *(const float4*)(&As[cur][k][tm*8]);
            *(float4*)(a + 4) = *(const float4*)(&As[cur][k][tm*8 + 4]);
            *(float4*)(b)     = *(const float4*)(&Bs[cur][k][tn*8]);
            *(float4*)(b + 4) = *(const float4*)(&Bs[cur][k][tn*8 + 4]);
#pragma unroll
            for (int i = 0; i < 8; ++i)
#pragma unroll
                for (int j = 0; j < 8; ++j)
                    acc[i][j] += a[i] * b[j];
        }
        if (t < 31) {
            int nxt = cur ^ 1;
            As[nxt][ac+0][ar] = ra0.x; As[nxt][ac+1][ar] = ra0.y;
            As[nxt][ac+2][ar] = ra0.z; As[nxt][ac+3][ar] = ra0.w;
            As[nxt][ac+0][ar+64] = ra1.x; As[nxt][ac+1][ar+64] = ra1.y;
            As[nxt][ac+2][ar+64] = ra1.z; As[nxt][ac+3][ar+64] = ra1.w;
            *(float4*)(&Bs[nxt][br][bc])   = rb0;
            *(float4*)(&Bs[nxt][br][bc+4]) = rb1;
            __syncthreads();
        }
    }

    int ccol = n0 + tn * 8;
    float4 bv0 = *(const float4*)(bias + ccol);
    float4 bv1 = *(const float4*)(bias + ccol + 4);
#pragma unroll
    for (int i = 0; i < 8; ++i) {
        int row = m0 + tm * 8 + i;
        float4 o0, o1;
        o0.x = acc[i][0] + bv0.x; o0.y = acc[i][1] + bv0.y;
        o0.z = acc[i][2] + bv0.z; o0.w = acc[i][3] + bv0.w;
        o1.x = acc[i][4] + bv1.x; o1.y = acc[i][5] + bv1.y;
        o1.z = acc[i][6] + bv1.z; o1.w = acc[i][7] + bv1.w;
        *(float4*)(C + (size_t)row * C_ + ccol)     = o0;
        *(float4*)(C + (size_t)row * C_ + ccol + 4) = o1;
    }
}

// ---------------------------------------------------------------------------
// Xp = hs @ Wp + bp   (512 -> 8)
__global__ void k_xp(const float* __restrict__ Wp, const float* __restrict__ bp) {
    int idx = blockIdx.x * blockDim.x + threadIdx.x;
    if (idx >= MFULL * H_) return;
    int row = idx >> 3, h = idx & 7;
    const float* hsr = g_hs + (size_t)row * C_;
    float s = bp[h];
#pragma unroll 8
    for (int k = 0; k < C_; k++) s += hsr[k] * Wp[k*H_ + h];
    g_Xp[idx] = s;
}

// ---------------------------------------------------------------------------
// rmsnorm helpers: block = 512 threads = one row; per-head (64-chunk) reduce
__device__ __forceinline__ float head_rms_scale(float x, int d, float* ws) {
    float s = x * x;
#pragma unroll
    for (int o = 16; o; o >>= 1) s += __shfl_xor_sync(0xffffffffu, s, o);
    if ((d & 31) == 0) ws[d >> 5] = s;
    __syncthreads();
    int h = d >> 6;
    float tot = ws[2*h] + ws[2*h + 1];
    return rsqrtf(tot * (1.0f/64.0f) + 1e-5f);
}

__global__ void k_khnorm(const float* __restrict__ gk) {
    __shared__ float ws[16];
    int row = blockIdx.x, d = threadIdx.x;
    float x = g_kh[(size_t)row*C_ + d];
    float r = head_rms_scale(x, d, ws);
    g_kh[(size_t)row*C_ + d] = x * r * gk[d & 63];
}

__global__ void k_qfull(const float* __restrict__ gq) {
    __shared__ float ws[16];
    int row = blockIdx.x, d = threadIdx.x, h = d >> 6;
    float x = g_Xq[(size_t)row*C_ + d];
    float r = head_rms_scale(x, d, ws);
    float c = g_Xp[row*H_ + h];
    g_Q[(size_t)row*C_ + d] = x * r * gq[d & 63] * c * COMB_SCALE;
}

__global__ void k_qrest(const float* __restrict__ gq) {
    __shared__ float ws[16];
    int row = blockIdx.x, d = threadIdx.x, h = d >> 6;   // row = b*256 + i
    int fr = (row >> 8) * T_ + (row & 255) * 4;
    const float* p = g_Xq + (size_t)fr*C_ + d;
    float x = 0.25f * (p[0] + p[C_] + p[2*C_] + p[3*C_]);
    float r = head_rms_scale(x, d, ws);
    const float* pc = g_Xp + fr*H_ + h;
    float c = 0.25f * (pc[0] + pc[H_] + pc[2*H_] + pc[3*H_]);
    g_Q[(size_t)(MFULL + row)*C_ + d] = x * r * gq[d & 63] * c * COMB_SCALE;
}

// ---------------------------------------------------------------------------
__global__ void k_init() {
    int i = blockIdx.x * blockDim.x + threadIdx.x;
    if (i < MTOT) g_keys[i] = 0ull;
    if (i < V_)   g_cnt[i]  = 0;
}

__device__ __forceinline__ unsigned fkey(float f) {
    unsigned u = __float_as_uint(f);
    return (u & 0x80000000u) ? ~u : (u | 0x80000000u);
}

// argmax_n dot(Q[m,:], kh[n,:]) -> g_keys[m].  NT gemm, fused argmax epilogue.
// BM=BN=128, BK=16, 256 threads, 8x8 per thread, double-buffered.
// grid = (V/128=32 n-tiles, MTOT/128=40 m-tiles)
__global__ __launch_bounds__(256, 2) void k_argmax(const float* __restrict__ Aq) {
    __shared__ float As[2][16][132];
    __shared__ float Bs[2][16][132];

    int tid = threadIdx.x;
    int tm = tid >> 4, tn = tid & 15;
    int m0 = blockIdx.y << 7, n0 = blockIdx.x << 7;
    int ar = tid >> 2, ac = (tid & 3) << 2;

    const float* Ap = Aq   + (size_t)(m0 + ar) * C_ + ac;
    const float* Bp = g_kh + (size_t)(n0 + ar) * C_ + ac;

    float4 ra0 = *(const float4*)Ap;
    float4 ra1 = *(const float4*)(Ap + 64 * C_);
    float4 rb0 = *(const float4*)Bp;
    float4 rb1 = *(const float4*)(Bp + 64 * C_);

    As[0][ac+0][ar] = ra0.x; As[0][ac+1][ar] = ra0.y;
    As[0][ac+2][ar] = ra0.z; As[0][ac+3][ar] = ra0.w;
    As[0][ac+0][ar+64] = ra1.x; As[0][ac+1][ar+64] = ra1.y;
    As[0][ac+2][ar+64] = ra1.z; As[0][ac+3][ar+64] = ra1.w;
    Bs[0][ac+0][ar] = rb0.x; Bs[0][ac+1][ar] = rb0.y;
    Bs[0][ac+2][ar] = rb0.z; Bs[0][ac+3][ar] = rb0.w;
    Bs[0][ac+0][ar+64] = rb1.x; Bs[0][ac+1][ar+64] = rb1.y;
    Bs[0][ac+2][ar+64] = rb1.z; Bs[0][ac+3][ar+64] = rb1.w;
    __syncthreads();

    float acc[8][8] = {};
    for (int t = 0; t < 32; ++t) {
        int cur = t & 1;
        if (t < 31) {
            Ap += 16; Bp += 16;
            ra0 = *(const float4*)Ap;
            ra1 = *(const float4*)(Ap + 64 * C_);
            rb0 = *(const float4*)Bp;
            rb1 = *(const float4*)(Bp + 64 * C_);
        }
#pragma unroll
        for (int k = 0; k < 16; ++k) {
            float a[8], b[8];
            *(float4*)(a)     = *(const float4*)(&As[cur][k][tm*8]);
            *(float4*)(a + 4) = *(const float4*)(&As[cur][k][tm*8 + 4]);
            *(float4*)(b)     = *(const float4*)(&Bs[cur][k][tn*8]);
            *(float4*)(b + 4) = *(const float4*)(&Bs[cur][k][tn*8 + 4]);
#pragma unroll
            for (int i = 0; i < 8; ++i)
#pragma unroll
                for (int j = 0; j < 8; ++j)
                    acc[i][j] += a[i] * b[j];
        }
        if (t < 31) {
            int nxt = cur ^ 1;
            As[nxt][ac+0][ar] = ra0.x; As[nxt][ac+1][ar] = ra0.y;
            As[nxt][ac+2][ar] = ra0.z; As[nxt][ac+3][ar] = ra0.w;
            As[nxt][ac+0][ar+64] = ra1.x; As[nxt][ac+1][ar+64] = ra1.y;
            As[nxt][ac+2][ar+64] = ra1.z; As[nxt][ac+3][ar+64] = ra1.w;
            Bs[nxt][ac+0][ar] = rb0.x; Bs[nxt][ac+1][ar] = rb0.y;
            Bs[nxt][ac+2][ar] = rb0.z; Bs[nxt][ac+3][ar] = rb0.w;
            Bs[nxt][ac+0][ar+64] = rb1.x; Bs[nxt][ac+1][ar+64] = rb1.y;
            Bs[nxt][ac+2][ar+64] = rb1.z; Bs[nxt][ac+3][ar+64] = rb1.w;
            __syncthreads();
        }
    }

    // fused argmax epilogue: pack (orderable-float, 4095-n) into u64, reduce
    __syncthreads();
    unsigned long long* red = (unsigned long long*)&As[0][0][0]; // reuse smem (16KB <= 16.9KB)
#pragma unroll
    for (int i = 0; i < 8; ++i) {
        unsigned long long best = 0ull;
#pragma unroll
        for (int j = 0; j < 8; ++j) {
            int n = n0 + tn*8 + j;
            unsigned long long key =
                ((unsigned long long)fkey(acc[i][j]) << 32) | (unsigned)(4095 - n);
            if (key > best) best = key;
        }
        red[(tm*8 + i)*16 + tn] = best;
    }
    __syncthreads();
    if (tid < 128) {
        unsigned long long b = red[tid*16];
#pragma unroll
        for (int t = 1; t < 16; t++) {
            unsigned long long v = red[tid*16 + t];
            if (v > b) b = v;
        }
        atomicMax(&g_keys[m0 + tid], b);
    }
}

// ---------------------------------------------------------------------------
__global__ void k_hist() {
    int i = blockIdx.x * blockDim.x + threadIdx.x;
    if (i < MFULL) {
        int n = 4095 - (int)(unsigned)(g_keys[i] & 0xFFFFFFFFull);
        atomicAdd(&g_cnt[n], 1);
    }
}

// z_hat gather + linear interp q=256 -> T=1024
__global__ void k_out(float* __restrict__ out) {
    int idx = blockIdx.x * blockDim.x + threadIdx.x;
    if (idx >= ZHAT_ELEMS) return;
    int t = idx & (T_ - 1);
    int d = (idx >> 10) & 511;
    int b = idx >> 19;
    float pos = (t + 0.5f) * ((float)Q_ / (float)T_) - 0.5f;
    pos = fminf(fmaxf(pos, 0.0f), (float)(Q_ - 1));
    int i0 = (int)pos;
    int i1 = min(i0 + 1, Q_ - 1);
    float w = pos - (float)i0;
    int n0 = 4095 - (int)(unsigned)(g_keys[MFULL + b*Q_ + i0] & 0xFFFFFFFFull);
    int n1 = 4095 - (int)(unsigned)(g_keys[MFULL + b*Q_ + i1] & 0xFFFFFFFFull);
    out[idx] = (1.0f - w) * g_value[(size_t)n0*C_ + d] + w * g_value[(size_t)n1*C_ + d];
}

__global__ void k_perp(float* __restrict__ out) {
    __shared__ float sm[1024];
    int tid = threadIdx.x;
    float s = 0.0f;
    for (int j = tid; j < V_; j += 1024) {
        float p = (float)g_cnt[j] * (1.0f / 4096.0f);
        s += p * logf(p + 1e-7f);
    }
    sm[tid] = s;
    __syncthreads();
    for (int o = 512; o; o >>= 1) {
        if (tid < o) sm[tid] += sm[tid + o];
        __syncthreads();
    }
    if (tid == 0) out[ZHAT_ELEMS] = expf(-sm[0]);
}

// ---------------------------------------------------------------------------
extern "C" void kernel_launch(void* const* d_in, const int* in_sizes, int n_in,
                              void* d_out, int out_size) {
    const float* z        = (const float*)d_in[0];
    const float* codebook = (const float*)d_in[2];
    const float* Wq = (const float*)d_in[3];
    const float* bq = (const float*)d_in[4];
    const float* Wk = (const float*)d_in[5];
    const float* bk = (const float*)d_in[6];
    const float* Wv = (const float*)d_in[7];
    const float* bv = (const float*)d_in[8];
    const float* Wp = (const float*)d_in[9];
    const float* bp = (const float*)d_in[10];
    const float* gq = (const float*)d_in[11];
    const float* gk = (const float*)d_in[12];
    float* out = (float*)d_out;

    float *p_Q;
    cudaGetSymbolAddress((void**)&p_Q, g_Q);

    k_transpose<<<dim3(16, 32, 4), dim3(32, 8)>>>(z);

    // all three 512x512 projections in one launch
    k_proj<<<dim3(4, 32, 3), 256>>>(codebook, Wq, bq, Wk, bk, Wv, bv);
    k_xp<<<(MFULL*H_ + 255)/256, 256>>>(Wp, bp);

    k_khnorm<<<V_,    512>>>(gk);
    k_qfull <<<MFULL, 512>>>(gq);
    k_qrest <<<MREST, 512>>>(gq);

    k_init<<<(MTOT + 255)/256, 256>>>();
    k_argmax<<<dim3(32, 40), 256>>>(p_Q);

    k_hist<<<16, 256>>>();
    k_out<<<(ZHAT_ELEMS + 255)/256, 256>>>(out);
    k_perp<<<1, 1024>>>(out);
}

// round 4
// speedup vs baseline: 1.7881x; 1.5902x over previous
#include <cuda_runtime.h>
#include <cstdint>

// Problem constants
#define B_    4
#define T_    1024
#define C_    512
#define V_    4096
#define H_    8
#define Q_    256
#define MFULL 4096
#define MREST 1024
#define MTOT  5120
#define ZHAT_ELEMS (B_*C_*T_)
#define COMB_SCALE 0.044194173824159216f

// ---- scratch ----
__device__ float g_hs[MFULL*C_];
__device__ float g_Xq[MFULL*C_];
__device__ float g_Xp[MFULL*H_];
__device__ float g_value[V_*C_];
__device__ float g_kh[V_*C_];
__device__ float g_Q[MTOT*C_];
__device__ float g_logits[(size_t)MTOT*V_];   // 84MB approx logits
__device__ float g_qnorm[MTOT];
__device__ int   g_knmax_i;
__device__ int   g_idx[MTOT];
__device__ int   g_cnt[V_];

// =====================  small kernels  =====================
__global__ void k_init() {
    int i = blockIdx.x * blockDim.x + threadIdx.x;
    if (i < V_) g_cnt[i] = 0;
    if (i == 0) g_knmax_i = 0;
}

__global__ void k_transpose(const float* __restrict__ z) {
    __shared__ float tile[32][33];
    int b = blockIdx.z, c0 = blockIdx.x << 5, t0 = blockIdx.y << 5;
    int tx = threadIdx.x, ty = threadIdx.y;
#pragma unroll
    for (int j = 0; j < 4; j++)
        tile[ty + 8*j][tx] = z[(b*C_ + c0 + ty + 8*j)*T_ + t0 + tx];
    __syncthreads();
#pragma unroll
    for (int j = 0; j < 4; j++)
        g_hs[(b*T_ + t0 + ty + 8*j)*C_ + c0 + tx] = tile[tx][ty + 8*j];
}

// Batched projection GEMM (fp32 SIMT, precision-critical)
__global__ __launch_bounds__(256, 2) void k_proj(
    const float* __restrict__ cb,
    const float* __restrict__ Wq, const float* __restrict__ bq,
    const float* __restrict__ Wk, const float* __restrict__ bk,
    const float* __restrict__ Wv, const float* __restrict__ bv) {
    __shared__ float As[2][16][132];
    __shared__ float Bs[2][16][132];
    const float *A, *Bm, *bias;
    float* C;
    int zid = blockIdx.z;
    if (zid == 0)      { A = g_hs; Bm = Wq; bias = bq; C = g_Xq; }
    else if (zid == 1) { A = cb;   Bm = Wk; bias = bk; C = g_kh; }
    else               { A = cb;   Bm = Wv; bias = bv; C = g_value; }
    int tid = threadIdx.x;
    int tm = tid >> 4, tn = tid & 15;
    int m0 = blockIdx.y << 7, n0 = blockIdx.x << 7;
    int ar = tid >> 2, ac = (tid & 3) << 2;
    int br = tid >> 4, bc = (tid & 15) << 3;
    const float* Ap = A  + (size_t)(m0 + ar) * C_ + ac;
    const float* Bp = Bm + (size_t)br * C_ + n0 + bc;
    float4 ra0 = *(const float4*)Ap;
    float4 ra1 = *(const float4*)(Ap + 64 * C_);
    float4 rb0 = *(const float4*)Bp;
    float4 rb1 = *(const float4*)(Bp + 4);
    As[0][ac+0][ar] = ra0.x; As[0][ac+1][ar] = ra0.y;
    As[0][ac+2][ar] = ra0.z; As[0][ac+3][ar] = ra0.w;
    As[0][ac+0][ar+64] = ra1.x; As[0][ac+1][ar+64] = ra1.y;
    As[0][ac+2][ar+64] = ra1.z; As[0][ac+3][ar+64] = ra1.w;
    *(float4*)(&Bs[0][br][bc])   = rb0;
    *(float4*)(&Bs[0][br][bc+4]) = rb1;
    __syncthreads();
    float acc[8][8] = {};
    for (int t = 0; t < 32; ++t) {
        int cur = t & 1;
        if (t < 31) {
            Ap += 16; Bp += 16 * C_;
            ra0 = *(const float4*)Ap;
            ra1 = *(const float4*)(Ap + 64 * C_);
            rb0 = *(const float4*)Bp;
            rb1 = *(const float4*)(Bp + 4);
        }
#pragma unroll
        for (int k = 0; k < 16; ++k) {
            float a[8], b[8];
            *(float4*)(a)     = *(const float4*)(&As[cur][k][tm*8]);
            *(float4*)(a + 4) = *(const float4*)(&As[cur][k][tm*8 + 4]);
            *(float4*)(b)     = *(const float4*)(&Bs[cur][k][tn*8]);
            *(float4*)(b + 4) = *(const float4*)(&Bs[cur][k][tn*8 + 4]);
#pragma unroll
            for (int i = 0; i < 8; ++i)
#pragma unroll
                for (int j = 0; j < 8; ++j)
                    acc[i][j] += a[i] * b[j];
        }
        if (t < 31) {
            int nxt = cur ^ 1;
            As[nxt][ac+0][ar] = ra0.x; As[nxt][ac+1][ar] = ra0.y;
            As[nxt][ac+2][ar] = ra0.z; As[nxt][ac+3][ar] = ra0.w;
            As[nxt][ac+0][ar+64] = ra1.x; As[nxt][ac+1][ar+64] = ra1.y;
            As[nxt][ac+2][ar+64] = ra1.z; As[nxt][ac+3][ar+64] = ra1.w;
            *(float4*)(&Bs[nxt][br][bc])   = rb0;
            *(float4*)(&Bs[nxt][br][bc+4]) = rb1;
            __syncthreads();
        }
    }
    int ccol = n0 + tn * 8;
    float4 bv0 = *(const float4*)(bias + ccol);
    float4 bv1 = *(const float4*)(bias + ccol + 4);
#pragma unroll
    for (int i = 0; i < 8; ++i) {
        int row = m0 + tm * 8 + i;
        float4 o0, o1;
        o0.x = acc[i][0] + bv0.x; o0.y = acc[i][1] + bv0.y;
        o0.z = acc[i][2] + bv0.z; o0.w = acc[i][3] + bv0.w;
        o1.x = acc[i][4] + bv1.x; o1.y = acc[i][5] + bv1.y;
        o1.z = acc[i][6] + bv1.z; o1.w = acc[i][7] + bv1.w;
        *(float4*)(C + (size_t)row * C_ + ccol)     = o0;
        *(float4*)(C + (size_t)row * C_ + ccol + 4) = o1;
    }
}

__global__ void k_xp(const float* __restrict__ Wp, const float* __restrict__ bp) {
    int idx = blockIdx.x * blockDim.x + threadIdx.x;
    if (idx >= MFULL * H_) return;
    int row = idx >> 3, h = idx & 7;
    const float* hsr = g_hs + (size_t)row * C_;
    float s = bp[h];
#pragma unroll 8
    for (int k = 0; k < C_; k++) s += hsr[k] * Wp[k*H_ + h];
    g_Xp[idx] = s;
}

__device__ __forceinline__ float head_rms_scale(float x, int d, float* ws) {
    float s = x * x;
#pragma unroll
    for (int o = 16; o; o >>= 1) s += __shfl_xor_sync(0xffffffffu, s, o);
    if ((d & 31) == 0) ws[d >> 5] = s;
    __syncthreads();
    int h = d >> 6;
    float tot = ws[2*h] + ws[2*h + 1];
    return rsqrtf(tot * (1.0f/64.0f) + 1e-5f);
}

__device__ __forceinline__ float block_sum_sq(float v, int d, float* s2) {
    float s = v * v;
#pragma unroll
    for (int o = 16; o; o >>= 1) s += __shfl_xor_sync(0xffffffffu, s, o);
    if ((d & 31) == 0) s2[d >> 5] = s;
    __syncthreads();
    float tot = 0.0f;
    if (d == 0) {
#pragma unroll
        for (int i = 0; i < 16; i++) tot += s2[i];
    }
    return tot;
}

__global__ void k_khnorm(const float* __restrict__ gk) {
    __shared__ float ws[16];
    __shared__ float s2[16];
    int row = blockIdx.x, d = threadIdx.x;
    float x = g_kh[(size_t)row*C_ + d];
    float r = head_rms_scale(x, d, ws);
    float v = x * r * gk[d & 63];
    g_kh[(size_t)row*C_ + d] = v;
    __syncthreads();
    float n2 = block_sum_sq(v, d, s2);
    if (d == 0) atomicMax(&g_knmax_i, __float_as_int(sqrtf(n2)));
}

__global__ void k_qfull(const float* __restrict__ gq) {
    __shared__ float ws[16];
    __shared__ float s2[16];
    int row = blockIdx.x, d = threadIdx.x, h = d >> 6;
    float x = g_Xq[(size_t)row*C_ + d];
    float r = head_rms_scale(x, d, ws);
    float c = g_Xp[row*H_ + h];
    float v = x * r * gq[d & 63] * c * COMB_SCALE;
    g_Q[(size_t)row*C_ + d] = v;
    __syncthreads();
    float n2 = block_sum_sq(v, d, s2);
    if (d == 0) g_qnorm[row] = sqrtf(n2);
}

__global__ void k_qrest(const float* __restrict__ gq) {
    __shared__ float ws[16];
    __shared__ float s2[16];
    int row = blockIdx.x, d = threadIdx.x, h = d >> 6;
    int fr = (row >> 8) * T_ + (row & 255) * 4;
    const float* p = g_Xq + (size_t)fr*C_ + d;
    float x = 0.25f * (p[0] + p[C_] + p[2*C_] + p[3*C_]);
    float r = head_rms_scale(x, d, ws);
    const float* pc = g_Xp + fr*H_ + h;
    float c = 0.25f * (pc[0] + pc[H_] + pc[2*H_] + pc[3*H_]);
    float v = x * r * gq[d & 63] * c * COMB_SCALE;
    g_Q[(size_t)(MFULL + row)*C_ + d] = v;
    __syncthreads();
    float n2 = block_sum_sq(v, d, s2);
    if (d == 0) g_qnorm[MFULL + row] = sqrtf(n2);
}

// =====================  tf32 mma.sync logits GEMM  =====================
// logits[m,n] = dot(Q[m,:], kh[n,:]).  CTA tile 128x128, 8 warps (4m x 2n),
// warp tile 32x64, BK=16 double buffered.  Operands cvt.rna.tf32 at smem store.
#define CVT4(d, v) do { \
    asm("cvt.rna.tf32.f32 %0, %1;" : "=r"((d).x) : "f"((v).x)); \
    asm("cvt.rna.tf32.f32 %0, %1;" : "=r"((d).y) : "f"((v).y)); \
    asm("cvt.rna.tf32.f32 %0, %1;" : "=r"((d).z) : "f"((v).z)); \
    asm("cvt.rna.tf32.f32 %0, %1;" : "=r"((d).w) : "f"((v).w)); \
} while (0)

#define MMA_TF32(c, a, b0, b1) \
    asm volatile("mma.sync.aligned.m16n8k8.row.col.f32.tf32.tf32.f32 " \
        "{%0,%1,%2,%3}, {%4,%5,%6,%7}, {%8,%9}, {%0,%1,%2,%3};" \
        : "+f"((c)[0]), "+f"((c)[1]), "+f"((c)[2]), "+f"((c)[3]) \
        : "r"((a)[0]), "r"((a)[1]), "r"((a)[2]), "r"((a)[3]), "r"(b0), "r"(b1))

__global__ __launch_bounds__(256, 2) void k_logits_mma() {
    // [row][k] layout, pad 20 words: conflict-free fragment loads, aligned uint4 stores
    __shared__ uint32_t As[2][128][20];
    __shared__ uint32_t Bs[2][128][20];
    const int tid = threadIdx.x;
    const int wid = tid >> 5, lane = tid & 31;
    const int warpM = wid >> 1, warpN = wid & 1;
    const int m0 = blockIdx.y << 7, n0 = blockIdx.x << 7;
    const int ar = tid >> 2, ac = (tid & 3) << 2;
    const int gid = lane >> 2, tig = lane & 3;

    const float* Ap = g_Q  + (size_t)(m0 + ar) * C_ + ac;
    const float* Bp = g_kh + (size_t)(n0 + ar) * C_ + ac;

    {
        float4 a0 = *(const float4*)Ap;
        float4 a1 = *(const float4*)(Ap + 64 * C_);
        float4 b0 = *(const float4*)Bp;
        float4 b1 = *(const float4*)(Bp + 64 * C_);
        uint4 u;
        CVT4(u, a0); *(uint4*)&As[0][ar][ac] = u;
        CVT4(u, a1); *(uint4*)&As[0][ar + 64][ac] = u;
        CVT4(u, b0); *(uint4*)&Bs[0][ar][ac] = u;
        CVT4(u, b1); *(uint4*)&Bs[0][ar + 64][ac] = u;
    }
    __syncthreads();

    float acc[2][8][4] = {};
    for (int t = 0; t < 32; ++t) {
        const int cur = t & 1;
        float4 pa0, pa1, pb0, pb1;
        if (t < 31) {
            const float* A2 = Ap + (t + 1) * 16;
            const float* B2 = Bp + (t + 1) * 16;
            pa0 = *(const float4*)A2;
            pa1 = *(const float4*)(A2 + 64 * C_);
            pb0 = *(const float4*)B2;
            pb1 = *(const float4*)(B2 + 64 * C_);
        }
#pragma unroll
        for (int ks = 0; ks < 16; ks += 8) {
            uint32_t af[2][4];
#pragma unroll
            for (int mt = 0; mt < 2; mt++) {
                int r = warpM * 32 + mt * 16 + gid;
                af[mt][0] = As[cur][r][ks + tig];
                af[mt][1] = As[cur][r + 8][ks + tig];
                af[mt][2] = As[cur][r][ks + tig + 4];
                af[mt][3] = As[cur][r + 8][ks + tig + 4];
            }
#pragma unroll
            for (int nt = 0; nt < 8; nt++) {
                int c = warpN * 64 + nt * 8 + gid;
                uint32_t b0 = Bs[cur][c][ks + tig];
                uint32_t b1 = Bs[cur][c][ks + tig + 4];
                MMA_TF32(acc[0][nt], af[0], b0, b1);
                MMA_TF32(acc[1][nt], af[1], b0, b1);
            }
        }
        if (t < 31) {
            const int nxt = cur ^ 1;
            uint4 u;
            CVT4(u, pa0); *(uint4*)&As[nxt][ar][ac] = u;
            CVT4(u, pa1); *(uint4*)&As[nxt][ar + 64][ac] = u;
            CVT4(u, pb0); *(uint4*)&Bs[nxt][ar][ac] = u;
            CVT4(u, pb1); *(uint4*)&Bs[nxt][ar + 64][ac] = u;
            __syncthreads();
        }
    }

    // epilogue: write approx logits
#pragma unroll
    for (int mt = 0; mt < 2; mt++) {
#pragma unroll
        for (int nt = 0; nt < 8; nt++) {
            int row = m0 + warpM * 32 + mt * 16 + gid;
            int col = n0 + warpN * 64 + nt * 8 + 2 * tig;
            float2 v0 = make_float2(acc[mt][nt][0], acc[mt][nt][1]);
            float2 v1 = make_float2(acc[mt][nt][2], acc[mt][nt][3]);
            *(float2*)(g_logits + (size_t)row * V_ + col)       = v0;
            *(float2*)(g_logits + (size_t)(row + 8) * V_ + col) = v1;
        }
    }
}

// =====================  margin select + exact rescore  =====================
__global__ __launch_bounds__(256, 4) void k_select() {
    __shared__ float s_red[8];
    __shared__ float s_bcast;
    __shared__ int   s_cnt;
    __shared__ int   s_cand[64];
    const int row = blockIdx.x;
    const int tid = threadIdx.x;
    const int wid = tid >> 5, lane = tid & 31;
    const float4* L = (const float4*)(g_logits + (size_t)row * V_);

    float4 v[4];
    float vmax = -1e30f;
#pragma unroll
    for (int j = 0; j < 4; j++) {
        v[j] = L[tid + j * 256];
        vmax = fmaxf(vmax, fmaxf(fmaxf(v[j].x, v[j].y), fmaxf(v[j].z, v[j].w)));
    }
#pragma unroll
    for (int o = 16; o; o >>= 1) vmax = fmaxf(vmax, __shfl_xor_sync(0xffffffffu, vmax, o));
    if (lane == 0) s_red[wid] = vmax;
    if (tid == 0) s_cnt = 0;
    __syncthreads();
    if (tid == 0) {
        float m = s_red[0];
#pragma unroll
        for (int i = 1; i < 8; i++) m = fmaxf(m, s_red[i]);
        s_bcast = m;
    }
    __syncthreads();
    const float kn = __int_as_float(g_knmax_i);
    const float margin = 0.0045f * g_qnorm[row] * kn + 1e-6f;
    const float thr = s_bcast - margin;

#pragma unroll
    for (int j = 0; j < 4; j++) {
        int nb = (tid + j * 256) * 4;
        float a[4] = {v[j].x, v[j].y, v[j].z, v[j].w};
#pragma unroll
        for (int c = 0; c < 4; c++) {
            if (a[c] >= thr) {
                int p = atomicAdd(&s_cnt, 1);
                if (p < 64) s_cand[p] = nb + c;
            }
        }
    }
    __syncthreads();
    int cnt = min(s_cnt, 64);

    const float* qr = g_Q + (size_t)row * C_;
    float best_v = -1e30f;
    int best_n = 1 << 30;
    for (int c = 0; c < cnt; c++) {
        int n = s_cand[c];
        const float* kr = g_kh + (size_t)n * C_;
        float p = qr[2*tid] * kr[2*tid] + qr[2*tid+1] * kr[2*tid+1];
#pragma unroll
        for (int o = 16; o; o >>= 1) p += __shfl_xor_sync(0xffffffffu, p, o);
        if (lane == 0) s_red[wid] = p;
        __syncthreads();
        if (tid == 0) {
            float sum = 0.0f;
#pragma unroll
            for (int i = 0; i < 8; i++) sum += s_red[i];
            s_bcast = sum;
        }
        __syncthreads();
        float val = s_bcast;
        if (val > best_v || (val == best_v && n < best_n)) { best_v = val; best_n = n; }
        __syncthreads();
    }
    if (tid == 0) g_idx[row] = best_n;
}

// =====================  output kernels  =====================
__global__ void k_hist() {
    int i = blockIdx.x * blockDim.x + threadIdx.x;
    if (i < MFULL) atomicAdd(&g_cnt[g_idx[i]], 1);
}

__global__ void k_out(float* __restrict__ out) {
    int idx = blockIdx.x * blockDim.x + threadIdx.x;
    if (idx >= ZHAT_ELEMS) return;
    int t = idx & (T_ - 1);
    int d = (idx >> 10) & 511;
    int b = idx >> 19;
    float pos = (t + 0.5f) * ((float)Q_ / (float)T_) - 0.5f;
    pos = fminf(fmaxf(pos, 0.0f), (float)(Q_ - 1));
    int i0 = (int)pos;
    int i1 = min(i0 + 1, Q_ - 1);
    float w = pos - (float)i0;
    int n0 = g_idx[MFULL + b*Q_ + i0];
    int n1 = g_idx[MFULL + b*Q_ + i1];
    out[idx] = (1.0f - w) * g_value[(size_t)n0*C_ + d] + w * g_value[(size_t)n1*C_ + d];
}

__global__ void k_perp(float* __restrict__ out) {
    __shared__ float sm_[1024];
    int tid = threadIdx.x;
    float s = 0.0f;
    for (int j = tid; j < V_; j += 1024) {
        float p = (float)g_cnt[j] * (1.0f / 4096.0f);
        s += p * logf(p + 1e-7f);
    }
    sm_[tid] = s;
    __syncthreads();
    for (int o = 512; o; o >>= 1) {
        if (tid < o) sm_[tid] += sm_[tid + o];
        __syncthreads();
    }
    if (tid == 0) out[ZHAT_ELEMS] = expf(-sm_[0]);
}

// ---------------------------------------------------------------------------
extern "C" void kernel_launch(void* const* d_in, const int* in_sizes, int n_in,
                              void* d_out, int out_size) {
    const float* z        = (const float*)d_in[0];
    const float* codebook = (const float*)d_in[2];
    const float* Wq = (const float*)d_in[3];
    const float* bq = (const float*)d_in[4];
    const float* Wk = (const float*)d_in[5];
    const float* bk = (const float*)d_in[6];
    const float* Wv = (const float*)d_in[7];
    const float* bv = (const float*)d_in[8];
    const float* Wp = (const float*)d_in[9];
    const float* bp = (const float*)d_in[10];
    const float* gq = (const float*)d_in[11];
    const float* gk = (const float*)d_in[12];
    float* out = (float*)d_out;

    k_init<<<(V_ + 255)/256, 256>>>();
    k_transpose<<<dim3(16, 32, 4), dim3(32, 8)>>>(z);
    k_proj<<<dim3(4, 32, 3), 256>>>(codebook, Wq, bq, Wk, bk, Wv, bv);
    k_xp<<<(MFULL*H_ + 255)/256, 256>>>(Wp, bp);

    k_khnorm<<<V_,    512>>>(gk);
    k_qfull <<<MFULL, 512>>>(gq);
    k_qrest <<<MREST, 512>>>(gq);

    // tf32 tensor-core logits: grid (V/128, MTOT/128)
    k_logits_mma<<<dim3(V_/128, MTOT/128), 256>>>();
    k_select<<<MTOT, 256>>>();

    k_hist<<<16, 256>>>();
    k_out<<<(ZHAT_ELEMS + 255)/256, 256>>>(out);
    k_perp<<<1, 1024>>>(out);
}

// round 5
// speedup vs baseline: 1.8985x; 1.0617x over previous
#include <cuda_runtime.h>
#include <cstdint>

// Problem constants
#define B_    4
#define T_    1024
#define C_    512
#define V_    4096
#define H_    8
#define Q_    256
#define MFULL 4096
#define MREST 1024
#define MTOT  5120
#define ZHAT_ELEMS (B_*C_*T_)
#define COMB_SCALE 0.044194173824159216f

// ---- scratch ----
__device__ float g_hs[MFULL*C_];
__device__ float g_Xq[MFULL*C_];
__device__ float g_Xp[MFULL*H_];
__device__ float g_value[V_*C_];
__device__ float g_kh[V_*C_];
__device__ float g_Q[MTOT*C_];
__device__ float g_logits[(size_t)MTOT*V_];
__device__ float g_qnorm[MTOT];
__device__ int   g_knmax_i;
__device__ int   g_idx[MTOT];
__device__ int   g_cnt[V_];

// =====================  mma helpers  =====================
#define MMA_TF32(c, a, b0, b1) \
    asm volatile("mma.sync.aligned.m16n8k8.row.col.f32.tf32.tf32.f32 " \
        "{%0,%1,%2,%3}, {%4,%5,%6,%7}, {%8,%9}, {%0,%1,%2,%3};" \
        : "+f"((c)[0]), "+f"((c)[1]), "+f"((c)[2]), "+f"((c)[3]) \
        : "r"((a)[0]), "r"((a)[1]), "r"((a)[2]), "r"((a)[3]), "r"(b0), "r"(b1))

__device__ __forceinline__ uint32_t tf32_of(float x) {
    uint32_t r; asm("cvt.rna.tf32.f32 %0, %1;" : "=r"(r) : "f"(x)); return r;
}
#define CVT4(d, v) do { \
    (d).x = tf32_of((v).x); (d).y = tf32_of((v).y); \
    (d).z = tf32_of((v).z); (d).w = tf32_of((v).w); \
} while (0)
// hi/lo split: x ~= hi + lo, |err| ~ 2^-22 |x|
#define SPLIT4(vh, vl, v) do { \
    (vh).x = tf32_of((v).x); (vl).x = tf32_of((v).x - __uint_as_float((vh).x)); \
    (vh).y = tf32_of((v).y); (vl).y = tf32_of((v).y - __uint_as_float((vh).y)); \
    (vh).z = tf32_of((v).z); (vl).z = tf32_of((v).z - __uint_as_float((vh).z)); \
    (vh).w = tf32_of((v).w); (vl).w = tf32_of((v).w - __uint_as_float((vh).w)); \
} while (0)

// =====================  small kernels  =====================
__global__ void k_init() {
    int i = blockIdx.x * blockDim.x + threadIdx.x;
    if (i < V_) g_cnt[i] = 0;
    if (i == 0) g_knmax_i = 0;
}

__global__ void k_transpose(const float* __restrict__ z) {
    __shared__ float tile[32][33];
    int b = blockIdx.z, c0 = blockIdx.x << 5, t0 = blockIdx.y << 5;
    int tx = threadIdx.x, ty = threadIdx.y;
#pragma unroll
    for (int j = 0; j < 4; j++)
        tile[ty + 8*j][tx] = z[(b*C_ + c0 + ty + 8*j)*T_ + t0 + tx];
    __syncthreads();
#pragma unroll
    for (int j = 0; j < 4; j++)
        g_hs[(b*T_ + t0 + ty + 8*j)*C_ + c0 + tx] = tile[tx][ty + 8*j];
}

// Xp = hs @ Wp + bp : Wp staged in smem (broadcast), 8 parallel chains/thread
__global__ __launch_bounds__(256) void k_xp(const float* __restrict__ Wp,
                                            const float* __restrict__ bp) {
    __shared__ float w[C_ * H_];
    int tid = threadIdx.x;
    for (int i = tid * 4; i < C_ * H_; i += 1024)
        *(float4*)&w[i] = *(const float4*)&Wp[i];
    __syncthreads();
    int row = blockIdx.x * 256 + tid;
    const float* hsr = g_hs + (size_t)row * C_;
    float acc[8];
#pragma unroll
    for (int j = 0; j < 8; j++) acc[j] = bp[j];
#pragma unroll 4
    for (int k = 0; k < C_; k += 4) {
        float4 hv = *(const float4*)(hsr + k);
        float h[4] = {hv.x, hv.y, hv.z, hv.w};
#pragma unroll
        for (int i = 0; i < 4; i++) {
            float4 wa = *(const float4*)&w[(k + i) * 8];
            float4 wb = *(const float4*)&w[(k + i) * 8 + 4];
            acc[0] += h[i] * wa.x; acc[1] += h[i] * wa.y;
            acc[2] += h[i] * wa.z; acc[3] += h[i] * wa.w;
            acc[4] += h[i] * wb.x; acc[5] += h[i] * wb.y;
            acc[6] += h[i] * wb.z; acc[7] += h[i] * wb.w;
        }
    }
    float4 o0 = make_float4(acc[0], acc[1], acc[2], acc[3]);
    float4 o1 = make_float4(acc[4], acc[5], acc[6], acc[7]);
    *(float4*)(g_Xp + row * 8)     = o0;
    *(float4*)(g_Xp + row * 8 + 4) = o1;
}

// =====================  split-tf32 projection GEMM  =====================
// C[4096 x 512] = A[4096 x 512] @ W[512 x 512] + bias, error ~1e-6 relative.
// CTA 128x128, BK=16 double-buffered, 8 warps (4M x 2N), warp 32x64.
// 3-term split: hi*hi + hi*lo + lo*hi.
#define PADA 20
#define PADB 136
#define AWRDS (128*PADA)     // per buffer
#define BWRDS (16*PADB)

__global__ __launch_bounds__(256, 2) void k_proj_mma(
    const float* __restrict__ cb,
    const float* __restrict__ Wq, const float* __restrict__ bq,
    const float* __restrict__ Wk, const float* __restrict__ bk,
    const float* __restrict__ Wv, const float* __restrict__ bv) {
    extern __shared__ __align__(16) unsigned char smraw[];
    uint32_t* AH = (uint32_t*)smraw;           // [2][128][PADA]
    uint32_t* AL = AH + 2 * AWRDS;
    uint32_t* BH = AL + 2 * AWRDS;             // [2][16][PADB]
    uint32_t* BL = BH + 2 * BWRDS;

    const float *A, *Bm, *bias; float* C;
    int zid = blockIdx.z;
    if (zid == 0)      { A = g_hs; Bm = Wq; bias = bq; C = g_Xq; }
    else if (zid == 1) { A = cb;   Bm = Wk; bias = bk; C = g_kh; }
    else               { A = cb;   Bm = Wv; bias = bv; C = g_value; }

    const int tid = threadIdx.x;
    const int wid = tid >> 5, lane = tid & 31;
    const int warpM = wid >> 1, warpN = wid & 1;
    const int m0 = blockIdx.y << 7, n0 = blockIdx.x << 7;
    const int ar = tid >> 2, ac = (tid & 3) << 2;
    const int br = tid >> 4, bc = (tid & 15) << 3;
    const int gid = lane >> 2, tig = lane & 3;

    const float* Ap = A  + (size_t)(m0 + ar) * C_ + ac;
    const float* Bp = Bm + (size_t)br * 512 + n0 + bc;

    // chunk 0 -> buffer 0
    {
        float4 va0 = *(const float4*)Ap;
        float4 va1 = *(const float4*)(Ap + 64 * C_);
        float4 vb0 = *(const float4*)Bp;
        float4 vb1 = *(const float4*)(Bp + 4);
        uint4 h, l;
        SPLIT4(h, l, va0); *(uint4*)&AH[ar*PADA + ac] = h; *(uint4*)&AL[ar*PADA + ac] = l;
        SPLIT4(h, l, va1); *(uint4*)&AH[(ar+64)*PADA + ac] = h; *(uint4*)&AL[(ar+64)*PADA + ac] = l;
        SPLIT4(h, l, vb0); *(uint4*)&BH[br*PADB + bc] = h; *(uint4*)&BL[br*PADB + bc] = l;
        SPLIT4(h, l, vb1); *(uint4*)&BH[br*PADB + bc + 4] = h; *(uint4*)&BL[br*PADB + bc + 4] = l;
    }
    __syncthreads();

    float acc[2][8][4] = {};
    for (int t = 0; t < 32; ++t) {
        const int cur = t & 1;
        const uint32_t ab = cur * AWRDS, bb = cur * BWRDS;
        float4 pa0, pa1, pb0, pb1;
        if (t < 31) {
            const float* A2 = Ap + (t + 1) * 16;
            const float* B2 = Bp + (size_t)(t + 1) * 16 * 512;
            pa0 = *(const float4*)A2;
            pa1 = *(const float4*)(A2 + 64 * C_);
            pb0 = *(const float4*)B2;
            pb1 = *(const float4*)(B2 + 4);
        }
#pragma unroll
        for (int ks = 0; ks < 16; ks += 8) {
            uint32_t ah[2][4], al[2][4];
#pragma unroll
            for (int mt = 0; mt < 2; mt++) {
                int r = warpM * 32 + mt * 16 + gid;
                ah[mt][0] = AH[ab + r*PADA + ks + tig];
                ah[mt][1] = AH[ab + (r+8)*PADA + ks + tig];
                ah[mt][2] = AH[ab + r*PADA + ks + tig + 4];
                ah[mt][3] = AH[ab + (r+8)*PADA + ks + tig + 4];
                al[mt][0] = AL[ab + r*PADA + ks + tig];
                al[mt][1] = AL[ab + (r+8)*PADA + ks + tig];
                al[mt][2] = AL[ab + r*PADA + ks + tig + 4];
                al[mt][3] = AL[ab + (r+8)*PADA + ks + tig + 4];
            }
#pragma unroll
            for (int nt = 0; nt < 8; nt++) {
                int c = warpN * 64 + nt * 8 + gid;
                uint32_t bh0 = BH[bb + (ks+tig)*PADB + c];
                uint32_t bh1 = BH[bb + (ks+tig+4)*PADB + c];
                uint32_t bl0 = BL[bb + (ks+tig)*PADB + c];
                uint32_t bl1 = BL[bb + (ks+tig+4)*PADB + c];
#pragma unroll
                for (int mt = 0; mt < 2; mt++) {
                    MMA_TF32(acc[mt][nt], ah[mt], bh0, bh1);
                    MMA_TF32(acc[mt][nt], ah[mt], bl0, bl1);
                    MMA_TF32(acc[mt][nt], al[mt], bh0, bh1);
                }
            }
        }
        if (t < 31) {
            const int nxt = cur ^ 1;
            const uint32_t ab2 = nxt * AWRDS, bb2 = nxt * BWRDS;
            uint4 h, l;
            SPLIT4(h, l, pa0); *(uint4*)&AH[ab2 + ar*PADA + ac] = h; *(uint4*)&AL[ab2 + ar*PADA + ac] = l;
            SPLIT4(h, l, pa1); *(uint4*)&AH[ab2 + (ar+64)*PADA + ac] = h; *(uint4*)&AL[ab2 + (ar+64)*PADA + ac] = l;
            SPLIT4(h, l, pb0); *(uint4*)&BH[bb2 + br*PADB + bc] = h; *(uint4*)&BL[bb2 + br*PADB + bc] = l;
            SPLIT4(h, l, pb1); *(uint4*)&BH[bb2 + br*PADB + bc + 4] = h; *(uint4*)&BL[bb2 + br*PADB + bc + 4] = l;
            __syncthreads();
        }
    }

#pragma unroll
    for (int mt = 0; mt < 2; mt++) {
#pragma unroll
        for (int nt = 0; nt < 8; nt++) {
            int row = m0 + warpM * 32 + mt * 16 + gid;
            int col = n0 + warpN * 64 + nt * 8 + 2 * tig;
            float b0 = bias[col], b1 = bias[col + 1];
            float2 v0 = make_float2(acc[mt][nt][0] + b0, acc[mt][nt][1] + b1);
            float2 v1 = make_float2(acc[mt][nt][2] + b0, acc[mt][nt][3] + b1);
            *(float2*)(C + (size_t)row * C_ + col)       = v0;
            *(float2*)(C + (size_t)(row + 8) * C_ + col) = v1;
        }
    }
}

// =====================  rmsnorm + combine kernels  =====================
__device__ __forceinline__ float head_rms_scale(float x, int d, float* ws) {
    float s = x * x;
#pragma unroll
    for (int o = 16; o; o >>= 1) s += __shfl_xor_sync(0xffffffffu, s, o);
    if ((d & 31) == 0) ws[d >> 5] = s;
    __syncthreads();
    int h = d >> 6;
    float tot = ws[2*h] + ws[2*h + 1];
    return rsqrtf(tot * (1.0f/64.0f) + 1e-5f);
}

__device__ __forceinline__ float block_sum_sq(float v, int d, float* s2) {
    float s = v * v;
#pragma unroll
    for (int o = 16; o; o >>= 1) s += __shfl_xor_sync(0xffffffffu, s, o);
    if ((d & 31) == 0) s2[d >> 5] = s;
    __syncthreads();
    float tot = 0.0f;
    if (d == 0) {
#pragma unroll
        for (int i = 0; i < 16; i++) tot += s2[i];
    }
    return tot;
}

__global__ void k_khnorm(const float* __restrict__ gk) {
    __shared__ float ws[16];
    __shared__ float s2[16];
    int row = blockIdx.x, d = threadIdx.x;
    float x = g_kh[(size_t)row*C_ + d];
    float r = head_rms_scale(x, d, ws);
    float v = x * r * gk[d & 63];
    g_kh[(size_t)row*C_ + d] = v;
    __syncthreads();
    float n2 = block_sum_sq(v, d, s2);
    if (d == 0) atomicMax(&g_knmax_i, __float_as_int(sqrtf(n2)));
}

__global__ void k_qfull(const float* __restrict__ gq) {
    __shared__ float ws[16];
    __shared__ float s2[16];
    int row = blockIdx.x, d = threadIdx.x, h = d >> 6;
    float x = g_Xq[(size_t)row*C_ + d];
    float r = head_rms_scale(x, d, ws);
    float c = g_Xp[row*H_ + h];
    float v = x * r * gq[d & 63] * c * COMB_SCALE;
    g_Q[(size_t)row*C_ + d] = v;
    __syncthreads();
    float n2 = block_sum_sq(v, d, s2);
    if (d == 0) g_qnorm[row] = sqrtf(n2);
}

__global__ void k_qrest(const float* __restrict__ gq) {
    __shared__ float ws[16];
    __shared__ float s2[16];
    int row = blockIdx.x, d = threadIdx.x, h = d >> 6;
    int fr = (row >> 8) * T_ + (row & 255) * 4;
    const float* p = g_Xq + (size_t)fr*C_ + d;
    float x = 0.25f * (p[0] + p[C_] + p[2*C_] + p[3*C_]);
    float r = head_rms_scale(x, d, ws);
    const float* pc = g_Xp + fr*H_ + h;
    float c = 0.25f * (pc[0] + pc[H_] + pc[2*H_] + pc[3*H_]);
    float v = x * r * gq[d & 63] * c * COMB_SCALE;
    g_Q[(size_t)(MFULL + row)*C_ + d] = v;
    __syncthreads();
    float n2 = block_sum_sq(v, d, s2);
    if (d == 0) g_qnorm[MFULL + row] = sqrtf(n2);
}

// =====================  tf32 mma.sync logits GEMM (NT)  =====================
__global__ __launch_bounds__(256, 2) void k_logits_mma() {
    __shared__ uint32_t As[2][128][20];
    __shared__ uint32_t Bs[2][128][20];
    const int tid = threadIdx.x;
    const int wid = tid >> 5, lane = tid & 31;
    const int warpM = wid >> 1, warpN = wid & 1;
    const int m0 = blockIdx.y << 7, n0 = blockIdx.x << 7;
    const int ar = tid >> 2, ac = (tid & 3) << 2;
    const int gid = lane >> 2, tig = lane & 3;

    const float* Ap = g_Q  + (size_t)(m0 + ar) * C_ + ac;
    const float* Bp = g_kh + (size_t)(n0 + ar) * C_ + ac;

    {
        float4 a0 = *(const float4*)Ap;
        float4 a1 = *(const float4*)(Ap + 64 * C_);
        float4 b0 = *(const float4*)Bp;
        float4 b1 = *(const float4*)(Bp + 64 * C_);
        uint4 u;
        CVT4(u, a0); *(uint4*)&As[0][ar][ac] = u;
        CVT4(u, a1); *(uint4*)&As[0][ar + 64][ac] = u;
        CVT4(u, b0); *(uint4*)&Bs[0][ar][ac] = u;
        CVT4(u, b1); *(uint4*)&Bs[0][ar + 64][ac] = u;
    }
    __syncthreads();

    float acc[2][8][4] = {};
    for (int t = 0; t < 32; ++t) {
        const int cur = t & 1;
        float4 pa0, pa1, pb0, pb1;
        if (t < 31) {
            const float* A2 = Ap + (t + 1) * 16;
            const float* B2 = Bp + (t + 1) * 16;
            pa0 = *(const float4*)A2;
            pa1 = *(const float4*)(A2 + 64 * C_);
            pb0 = *(const float4*)B2;
            pb1 = *(const float4*)(B2 + 64 * C_);
        }
#pragma unroll
        for (int ks = 0; ks < 16; ks += 8) {
            uint32_t af[2][4];
#pragma unroll
            for (int mt = 0; mt < 2; mt++) {
                int r = warpM * 32 + mt * 16 + gid;
                af[mt][0] = As[cur][r][ks + tig];
                af[mt][1] = As[cur][r + 8][ks + tig];
                af[mt][2] = As[cur][r][ks + tig + 4];
                af[mt][3] = As[cur][r + 8][ks + tig + 4];
            }
#pragma unroll
            for (int nt = 0; nt < 8; nt++) {
                int c = warpN * 64 + nt * 8 + gid;
                uint32_t b0 = Bs[cur][c][ks + tig];
                uint32_t b1 = Bs[cur][c][ks + tig + 4];
                MMA_TF32(acc[0][nt], af[0], b0, b1);
                MMA_TF32(acc[1][nt], af[1], b0, b1);
            }
        }
        if (t < 31) {
            const int nxt = cur ^ 1;
            uint4 u;
            CVT4(u, pa0); *(uint4*)&As[nxt][ar][ac] = u;
            CVT4(u, pa1); *(uint4*)&As[nxt][ar + 64][ac] = u;
            CVT4(u, pb0); *(uint4*)&Bs[nxt][ar][ac] = u;
            CVT4(u, pb1); *(uint4*)&Bs[nxt][ar + 64][ac] = u;
            __syncthreads();
        }
    }

#pragma unroll
    for (int mt = 0; mt < 2; mt++) {
#pragma unroll
        for (int nt = 0; nt < 8; nt++) {
            int row = m0 + warpM * 32 + mt * 16 + gid;
            int col = n0 + warpN * 64 + nt * 8 + 2 * tig;
            float2 v0 = make_float2(acc[mt][nt][0], acc[mt][nt][1]);
            float2 v1 = make_float2(acc[mt][nt][2], acc[mt][nt][3]);
            *(float2*)(g_logits + (size_t)row * V_ + col)       = v0;
            *(float2*)(g_logits + (size_t)(row + 8) * V_ + col) = v1;
        }
    }
}

// =====================  margin select + exact rescore  =====================
__global__ __launch_bounds__(256, 4) void k_select() {
    __shared__ float s_red[8];
    __shared__ float s_bcast;
    __shared__ int   s_cnt;
    __shared__ int   s_cand[64];
    const int row = blockIdx.x;
    const int tid = threadIdx.x;
    const int wid = tid >> 5, lane = tid & 31;
    const float4* L = (const float4*)(g_logits + (size_t)row * V_);

    float4 v[4];
    float vmax = -1e30f;
#pragma unroll
    for (int j = 0; j < 4; j++) {
        v[j] = L[tid + j * 256];
        vmax = fmaxf(vmax, fmaxf(fmaxf(v[j].x, v[j].y), fmaxf(v[j].z, v[j].w)));
    }
#pragma unroll
    for (int o = 16; o; o >>= 1) vmax = fmaxf(vmax, __shfl_xor_sync(0xffffffffu, vmax, o));
    if (lane == 0) s_red[wid] = vmax;
    if (tid == 0) s_cnt = 0;
    __syncthreads();
    if (tid == 0) {
        float m = s_red[0];
#pragma unroll
        for (int i = 1; i < 8; i++) m = fmaxf(m, s_red[i]);
        s_bcast = m;
    }
    __syncthreads();
    const float kn = __int_as_float(g_knmax_i);
    const float margin = 0.0045f * g_qnorm[row] * kn + 1e-6f;
    const float thr = s_bcast - margin;

#pragma unroll
    for (int j = 0; j < 4; j++) {
        int nb = (tid + j * 256) * 4;
        float a[4] = {v[j].x, v[j].y, v[j].z, v[j].w};
#pragma unroll
        for (int c = 0; c < 4; c++) {
            if (a[c] >= thr) {
                int p = atomicAdd(&s_cnt, 1);
                if (p < 64) s_cand[p] = nb + c;
            }
        }
    }
    __syncthreads();
    int cnt = min(s_cnt, 64);

    const float* qr = g_Q + (size_t)row * C_;
    float best_v = -1e30f;
    int best_n = 1 << 30;
    for (int c = 0; c < cnt; c++) {
        int n = s_cand[c];
        const float* kr = g_kh + (size_t)n * C_;
        float p = qr[2*tid] * kr[2*tid] + qr[2*tid+1] * kr[2*tid+1];
#pragma unroll
        for (int o = 16; o; o >>= 1) p += __shfl_xor_sync(0xffffffffu, p, o);
        if (lane == 0) s_red[wid] = p;
        __syncthreads();
        if (tid == 0) {
            float sum = 0.0f;
#pragma unroll
            for (int i = 0; i < 8; i++) sum += s_red[i];
            s_bcast = sum;
        }
        __syncthreads();
        float val = s_bcast;
        if (val > best_v || (val == best_v && n < best_n)) { best_v = val; best_n = n; }
        __syncthreads();
    }
    if (tid == 0) g_idx[row] = best_n;
}

// =====================  output kernels  =====================
__global__ void k_hist() {
    int i = blockIdx.x * blockDim.x + threadIdx.x;
    if (i < MFULL) atomicAdd(&g_cnt[g_idx[i]], 1);
}

__global__ void k_out(float* __restrict__ out) {
    int idx = blockIdx.x * blockDim.x + threadIdx.x;
    if (idx >= ZHAT_ELEMS) return;
    int t = idx & (T_ - 1);
    int d = (idx >> 10) & 511;
    int b = idx >> 19;
    float pos = (t + 0.5f) * ((float)Q_ / (float)T_) - 0.5f;
    pos = fminf(fmaxf(pos, 0.0f), (float)(Q_ - 1));
    int i0 = (int)pos;
    int i1 = min(i0 + 1, Q_ - 1);
    float w = pos - (float)i0;
    int n0 = g_idx[MFULL + b*Q_ + i0];
    int n1 = g_idx[MFULL + b*Q_ + i1];
    out[idx] = (1.0f - w) * g_value[(size_t)n0*C_ + d] + w * g_value[(size_t)n1*C_ + d];
}

__global__ void k_perp(float* __restrict__ out) {
    __shared__ float sm_[1024];
    int tid = threadIdx.x;
    float s = 0.0f;
    for (int j = tid; j < V_; j += 1024) {
        float p = (float)g_cnt[j] * (1.0f / 4096.0f);
        s += p * logf(p + 1e-7f);
    }
    sm_[tid] = s;
    __syncthreads();
    for (int o = 512; o; o >>= 1) {
        if (tid < o) sm_[tid] += sm_[tid + o];
        __syncthreads();
    }
    if (tid == 0) out[ZHAT_ELEMS] = expf(-sm_[0]);
}

// ---------------------------------------------------------------------------
extern "C" void kernel_launch(void* const* d_in, const int* in_sizes, int n_in,
                              void* d_out, int out_size) {
    const float* z        = (const float*)d_in[0];
    const float* codebook = (const float*)d_in[2];
    const float* Wq = (const float*)d_in[3];
    const float* bq = (const float*)d_in[4];
    const float* Wk = (const float*)d_in[5];
    const float* bk = (const float*)d_in[6];
    const float* Wv = (const float*)d_in[7];
    const float* bv = (const float*)d_in[8];
    const float* Wp = (const float*)d_in[9];
    const float* bp = (const float*)d_in[10];
    const float* gq = (const float*)d_in[11];
    const float* gk = (const float*)d_in[12];
    float* out = (float*)d_out;

    const int proj_smem = (2*AWRDS + 2*AWRDS + 2*BWRDS + 2*BWRDS) * 4; // 75776
    cudaFuncSetAttribute(k_proj_mma, cudaFuncAttributeMaxDynamicSharedMemorySize, proj_smem);

    // slot-4 profiling: k_proj_mma lands at launch #4
    k_transpose<<<dim3(16, 32, 4), dim3(32, 8)>>>(z);           // 1
    k_xp<<<16, 256>>>(Wp, bp);                                  // 2
    k_init<<<(V_ + 255)/256, 256>>>();                          // 3
    k_proj_mma<<<dim3(4, 32, 3), 256, proj_smem>>>(codebook, Wq, bq, Wk, bk, Wv, bv); // 4

    k_khnorm<<<V_,    512>>>(gk);
    k_qfull <<<MFULL, 512>>>(gq);
    k_qrest <<<MREST, 512>>>(gq);

    k_logits_mma<<<dim3(V_/128, MTOT/128), 256>>>();
    k_select<<<MTOT, 256>>>();

    k_hist<<<16, 256>>>();
    k_out<<<(ZHAT_ELEMS + 255)/256, 256>>>(out);
    k_perp<<<1, 1024>>>(out);
}

// round 6
// speedup vs baseline: 2.1909x; 1.1540x over previous
#include <cuda_runtime.h>
#include <cuda_bf16.h>
#include <cstdint>

// Problem constants
#define B_    4
#define T_    1024
#define C_    512
#define V_    4096
#define H_    8
#define Q_    256
#define MFULL 4096
#define MREST 1024
#define MTOT  5120
#define ZHAT_ELEMS (B_*C_*T_)
#define COMB_SCALE 0.044194173824159216f

// ---- scratch ----
__device__ float g_hs[MFULL*C_];
__device__ float g_Xq[MFULL*C_];
__device__ float g_Xp[MFULL*H_];
__device__ float g_value[V_*C_];
__device__ float g_kh[V_*C_];
__device__ float g_Q[MTOT*C_];
__device__ __nv_bfloat16 g_Qh[MTOT*C_];   // bf16 copies for logits MMA
__device__ __nv_bfloat16 g_Kh[V_*C_];
__device__ float g_logits[(size_t)MTOT*V_];
__device__ float g_qnorm[MTOT];
__device__ int   g_knmax_i;
__device__ int   g_idx[MTOT];
__device__ int   g_cnt[V_];

// =====================  mma helpers  =====================
#define MMA_TF32(c, a, b0, b1) \
    asm volatile("mma.sync.aligned.m16n8k8.row.col.f32.tf32.tf32.f32 " \
        "{%0,%1,%2,%3}, {%4,%5,%6,%7}, {%8,%9}, {%0,%1,%2,%3};" \
        : "+f"((c)[0]), "+f"((c)[1]), "+f"((c)[2]), "+f"((c)[3]) \
        : "r"((a)[0]), "r"((a)[1]), "r"((a)[2]), "r"((a)[3]), "r"(b0), "r"(b1))

#define MMA_BF16(c, a, b0, b1) \
    asm volatile("mma.sync.aligned.m16n8k16.row.col.f32.bf16.bf16.f32 " \
        "{%0,%1,%2,%3}, {%4,%5,%6,%7}, {%8,%9}, {%0,%1,%2,%3};" \
        : "+f"((c)[0]), "+f"((c)[1]), "+f"((c)[2]), "+f"((c)[3]) \
        : "r"((a)[0]), "r"((a)[1]), "r"((a)[2]), "r"((a)[3]), "r"(b0), "r"(b1))

__device__ __forceinline__ uint32_t tf32_of(float x) {
    uint32_t r; asm("cvt.rna.tf32.f32 %0, %1;" : "=r"(r) : "f"(x)); return r;
}
#define SPLIT4(vh, vl, v) do { \
    (vh).x = tf32_of((v).x); (vl).x = tf32_of((v).x - __uint_as_float((vh).x)); \
    (vh).y = tf32_of((v).y); (vl).y = tf32_of((v).y - __uint_as_float((vh).y)); \
    (vh).z = tf32_of((v).z); (vl).z = tf32_of((v).z - __uint_as_float((vh).z)); \
    (vh).w = tf32_of((v).w); (vl).w = tf32_of((v).w - __uint_as_float((vh).w)); \
} while (0)

// =====================  small kernels  =====================
__global__ void k_init() {
    int i = blockIdx.x * blockDim.x + threadIdx.x;
    if (i < V_) g_cnt[i] = 0;
    if (i == 0) g_knmax_i = 0;
}

__global__ void k_transpose(const float* __restrict__ z) {
    __shared__ float tile[32][33];
    int b = blockIdx.z, c0 = blockIdx.x << 5, t0 = blockIdx.y << 5;
    int tx = threadIdx.x, ty = threadIdx.y;
#pragma unroll
    for (int j = 0; j < 4; j++)
        tile[ty + 8*j][tx] = z[(b*C_ + c0 + ty + 8*j)*T_ + t0 + tx];
    __syncthreads();
#pragma unroll
    for (int j = 0; j < 4; j++)
        g_hs[(b*T_ + t0 + ty + 8*j)*C_ + c0 + tx] = tile[tx][ty + 8*j];
}

__global__ __launch_bounds__(256) void k_xp(const float* __restrict__ Wp,
                                            const float* __restrict__ bp) {
    __shared__ float w[C_ * H_];
    int tid = threadIdx.x;
    for (int i = tid * 4; i < C_ * H_; i += 1024)
        *(float4*)&w[i] = *(const float4*)&Wp[i];
    __syncthreads();
    int row = blockIdx.x * 256 + tid;
    const float* hsr = g_hs + (size_t)row * C_;
    float acc[8];
#pragma unroll
    for (int j = 0; j < 8; j++) acc[j] = bp[j];
#pragma unroll 4
    for (int k = 0; k < C_; k += 4) {
        float4 hv = *(const float4*)(hsr + k);
        float h[4] = {hv.x, hv.y, hv.z, hv.w};
#pragma unroll
        for (int i = 0; i < 4; i++) {
            float4 wa = *(const float4*)&w[(k + i) * 8];
            float4 wb = *(const float4*)&w[(k + i) * 8 + 4];
            acc[0] += h[i] * wa.x; acc[1] += h[i] * wa.y;
            acc[2] += h[i] * wa.z; acc[3] += h[i] * wa.w;
            acc[4] += h[i] * wb.x; acc[5] += h[i] * wb.y;
            acc[6] += h[i] * wb.z; acc[7] += h[i] * wb.w;
        }
    }
    *(float4*)(g_Xp + row * 8)     = make_float4(acc[0], acc[1], acc[2], acc[3]);
    *(float4*)(g_Xp + row * 8 + 4) = make_float4(acc[4], acc[5], acc[6], acc[7]);
}

// =====================  split-tf32 projection GEMM  =====================
#define PADA 20
#define PADB 136
#define AWRDS (128*PADA)
#define BWRDS (16*PADB)

__global__ __launch_bounds__(256, 2) void k_proj_mma(
    const float* __restrict__ cb,
    const float* __restrict__ Wq, const float* __restrict__ bq,
    const float* __restrict__ Wk, const float* __restrict__ bk,
    const float* __restrict__ Wv, const float* __restrict__ bv) {
    extern __shared__ __align__(16) unsigned char smraw[];
    uint32_t* AH = (uint32_t*)smraw;
    uint32_t* AL = AH + 2 * AWRDS;
    uint32_t* BH = AL + 2 * AWRDS;
    uint32_t* BL = BH + 2 * BWRDS;

    const float *A, *Bm, *bias; float* C;
    int zid = blockIdx.z;
    if (zid == 0)      { A = g_hs; Bm = Wq; bias = bq; C = g_Xq; }
    else if (zid == 1) { A = cb;   Bm = Wk; bias = bk; C = g_kh; }
    else               { A = cb;   Bm = Wv; bias = bv; C = g_value; }

    const int tid = threadIdx.x;
    const int wid = tid >> 5, lane = tid & 31;
    const int warpM = wid >> 1, warpN = wid & 1;
    const int m0 = blockIdx.y << 7, n0 = blockIdx.x << 7;
    const int ar = tid >> 2, ac = (tid & 3) << 2;
    const int br = tid >> 4, bc = (tid & 15) << 3;
    const int gid = lane >> 2, tig = lane & 3;

    const float* Ap = A  + (size_t)(m0 + ar) * C_ + ac;
    const float* Bp = Bm + (size_t)br * 512 + n0 + bc;

    {
        float4 va0 = *(const float4*)Ap;
        float4 va1 = *(const float4*)(Ap + 64 * C_);
        float4 vb0 = *(const float4*)Bp;
        float4 vb1 = *(const float4*)(Bp + 4);
        uint4 h, l;
        SPLIT4(h, l, va0); *(uint4*)&AH[ar*PADA + ac] = h; *(uint4*)&AL[ar*PADA + ac] = l;
        SPLIT4(h, l, va1); *(uint4*)&AH[(ar+64)*PADA + ac] = h; *(uint4*)&AL[(ar+64)*PADA + ac] = l;
        SPLIT4(h, l, vb0); *(uint4*)&BH[br*PADB + bc] = h; *(uint4*)&BL[br*PADB + bc] = l;
        SPLIT4(h, l, vb1); *(uint4*)&BH[br*PADB + bc + 4] = h; *(uint4*)&BL[br*PADB + bc + 4] = l;
    }
    __syncthreads();

    float acc[2][8][4] = {};
    for (int t = 0; t < 32; ++t) {
        const int cur = t & 1;
        const uint32_t ab = cur * AWRDS, bb = cur * BWRDS;
        float4 pa0, pa1, pb0, pb1;
        if (t < 31) {
            const float* A2 = Ap + (t + 1) * 16;
            const float* B2 = Bp + (size_t)(t + 1) * 16 * 512;
            pa0 = *(const float4*)A2;
            pa1 = *(const float4*)(A2 + 64 * C_);
            pb0 = *(const float4*)B2;
            pb1 = *(const float4*)(B2 + 4);
        }
#pragma unroll
        for (int ks = 0; ks < 16; ks += 8) {
            uint32_t ah[2][4], al[2][4];
#pragma unroll
            for (int mt = 0; mt < 2; mt++) {
                int r = warpM * 32 + mt * 16 + gid;
                ah[mt][0] = AH[ab + r*PADA + ks + tig];
                ah[mt][1] = AH[ab + (r+8)*PADA + ks + tig];
                ah[mt][2] = AH[ab + r*PADA + ks + tig + 4];
                ah[mt][3] = AH[ab + (r+8)*PADA + ks + tig + 4];
                al[mt][0] = AL[ab + r*PADA + ks + tig];
                al[mt][1] = AL[ab + (r+8)*PADA + ks + tig];
                al[mt][2] = AL[ab + r*PADA + ks + tig + 4];
                al[mt][3] = AL[ab + (r+8)*PADA + ks + tig + 4];
            }
#pragma unroll
            for (int nt = 0; nt < 8; nt++) {
                int c = warpN * 64 + nt * 8 + gid;
                uint32_t bh0 = BH[bb + (ks+tig)*PADB + c];
                uint32_t bh1 = BH[bb + (ks+tig+4)*PADB + c];
                uint32_t bl0 = BL[bb + (ks+tig)*PADB + c];
                uint32_t bl1 = BL[bb + (ks+tig+4)*PADB + c];
#pragma unroll
                for (int mt = 0; mt < 2; mt++) {
                    MMA_TF32(acc[mt][nt], ah[mt], bh0, bh1);
                    MMA_TF32(acc[mt][nt], ah[mt], bl0, bl1);
                    MMA_TF32(acc[mt][nt], al[mt], bh0, bh1);
                }
            }
        }
        if (t < 31) {
            const int nxt = cur ^ 1;
            const uint32_t ab2 = nxt * AWRDS, bb2 = nxt * BWRDS;
            uint4 h, l;
            SPLIT4(h, l, pa0); *(uint4*)&AH[ab2 + ar*PADA + ac] = h; *(uint4*)&AL[ab2 + ar*PADA + ac] = l;
            SPLIT4(h, l, pa1); *(uint4*)&AH[ab2 + (ar+64)*PADA + ac] = h; *(uint4*)&AL[ab2 + (ar+64)*PADA + ac] = l;
            SPLIT4(h, l, pb0); *(uint4*)&BH[bb2 + br*PADB + bc] = h; *(uint4*)&BL[bb2 + br*PADB + bc] = l;
            SPLIT4(h, l, pb1); *(uint4*)&BH[bb2 + br*PADB + bc + 4] = h; *(uint4*)&BL[bb2 + br*PADB + bc + 4] = l;
            __syncthreads();
        }
    }

#pragma unroll
    for (int mt = 0; mt < 2; mt++) {
#pragma unroll
        for (int nt = 0; nt < 8; nt++) {
            int row = m0 + warpM * 32 + mt * 16 + gid;
            int col = n0 + warpN * 64 + nt * 8 + 2 * tig;
            float b0 = bias[col], b1 = bias[col + 1];
            float2 v0 = make_float2(acc[mt][nt][0] + b0, acc[mt][nt][1] + b1);
            float2 v1 = make_float2(acc[mt][nt][2] + b0, acc[mt][nt][3] + b1);
            *(float2*)(C + (size_t)row * C_ + col)       = v0;
            *(float2*)(C + (size_t)(row + 8) * C_ + col) = v1;
        }
    }
}

// =====================  rmsnorm + combine kernels  =====================
__device__ __forceinline__ float head_rms_scale(float x, int d, float* ws) {
    float s = x * x;
#pragma unroll
    for (int o = 16; o; o >>= 1) s += __shfl_xor_sync(0xffffffffu, s, o);
    if ((d & 31) == 0) ws[d >> 5] = s;
    __syncthreads();
    int h = d >> 6;
    float tot = ws[2*h] + ws[2*h + 1];
    return rsqrtf(tot * (1.0f/64.0f) + 1e-5f);
}

__device__ __forceinline__ float block_sum_sq(float v, int d, float* s2) {
    float s = v * v;
#pragma unroll
    for (int o = 16; o; o >>= 1) s += __shfl_xor_sync(0xffffffffu, s, o);
    if ((d & 31) == 0) s2[d >> 5] = s;
    __syncthreads();
    float tot = 0.0f;
    if (d == 0) {
#pragma unroll
        for (int i = 0; i < 16; i++) tot += s2[i];
    }
    return tot;
}

__global__ void k_khnorm(const float* __restrict__ gk) {
    __shared__ float ws[16];
    __shared__ float s2[16];
    int row = blockIdx.x, d = threadIdx.x;
    float x = g_kh[(size_t)row*C_ + d];
    float r = head_rms_scale(x, d, ws);
    float v = x * r * gk[d & 63];
    g_kh[(size_t)row*C_ + d] = v;
    g_Kh[(size_t)row*C_ + d] = __float2bfloat16(v);
    __syncthreads();
    float n2 = block_sum_sq(v, d, s2);
    if (d == 0) atomicMax(&g_knmax_i, __float_as_int(sqrtf(n2)));
}

__global__ void k_qfull(const float* __restrict__ gq) {
    __shared__ float ws[16];
    __shared__ float s2[16];
    int row = blockIdx.x, d = threadIdx.x, h = d >> 6;
    float x = g_Xq[(size_t)row*C_ + d];
    float r = head_rms_scale(x, d, ws);
    float c = g_Xp[row*H_ + h];
    float v = x * r * gq[d & 63] * c * COMB_SCALE;
    g_Q[(size_t)row*C_ + d] = v;
    g_Qh[(size_t)row*C_ + d] = __float2bfloat16(v);
    __syncthreads();
    float n2 = block_sum_sq(v, d, s2);
    if (d == 0) g_qnorm[row] = sqrtf(n2);
}

__global__ void k_qrest(const float* __restrict__ gq) {
    __shared__ float ws[16];
    __shared__ float s2[16];
    int row = blockIdx.x, d = threadIdx.x, h = d >> 6;
    int fr = (row >> 8) * T_ + (row & 255) * 4;
    const float* p = g_Xq + (size_t)fr*C_ + d;
    float x = 0.25f * (p[0] + p[C_] + p[2*C_] + p[3*C_]);
    float r = head_rms_scale(x, d, ws);
    const float* pc = g_Xp + fr*H_ + h;
    float c = 0.25f * (pc[0] + pc[H_] + pc[2*H_] + pc[3*H_]);
    float v = x * r * gq[d & 63] * c * COMB_SCALE;
    g_Q[(size_t)(MFULL + row)*C_ + d] = v;
    g_Qh[(size_t)(MFULL + row)*C_ + d] = __float2bfloat16(v);
    __syncthreads();
    float n2 = block_sum_sq(v, d, s2);
    if (d == 0) g_qnorm[MFULL + row] = sqrtf(n2);
}

// =====================  bf16 mma.sync logits GEMM (NT)  =====================
// approx logits = Qh @ Kh^T.  CTA 128x128, BK=32 halves, double buffered.
// 8 warps (4M x 2N), warp tile 32x64, m16n8k16.
#define LPAD 20   // uints per 32-half row segment (16 data + 4 pad)

__global__ __launch_bounds__(256, 2) void k_logits_mma() {
    __shared__ uint32_t As[2][128][LPAD];
    __shared__ uint32_t Bs[2][128][LPAD];
    const int tid = threadIdx.x;
    const int wid = tid >> 5, lane = tid & 31;
    const int warpM = wid >> 1, warpN = wid & 1;
    const int m0 = blockIdx.y << 7, n0 = blockIdx.x << 7;
    const int gid = lane >> 2, tig = lane & 3;
    const int row = tid >> 1, hf = tid & 1;   // loader: 128 rows x 2 half-segments

    // each row-chunk = 32 halves = 4 uint4; thread handles 2 uint4
    const uint4* Ag = (const uint4*)(g_Qh + (size_t)(m0 + row) * C_) + hf * 2;
    const uint4* Bg = (const uint4*)(g_Kh + (size_t)(n0 + row) * C_) + hf * 2;

    {
        uint4 a0 = Ag[0], a1 = Ag[1];
        uint4 b0 = Bg[0], b1 = Bg[1];
        *(uint4*)&As[0][row][hf*8]     = a0;
        *(uint4*)&As[0][row][hf*8 + 4] = a1;
        *(uint4*)&Bs[0][row][hf*8]     = b0;
        *(uint4*)&Bs[0][row][hf*8 + 4] = b1;
    }
    __syncthreads();

    float acc[2][8][4] = {};
    for (int t = 0; t < 16; ++t) {           // 16 chunks x 32 halves = K 512
        const int cur = t & 1;
        uint4 pa0, pa1, pb0, pb1;
        if (t < 15) {
            const uint4* A2 = Ag + (t + 1) * 4;
            const uint4* B2 = Bg + (t + 1) * 4;
            pa0 = A2[0]; pa1 = A2[1];
            pb0 = B2[0]; pb1 = B2[1];
        }
#pragma unroll
        for (int ku = 0; ku < 16; ku += 8) { // two k16 steps per chunk
            uint32_t af[2][4];
#pragma unroll
            for (int mt = 0; mt < 2; mt++) {
                int r = warpM * 32 + mt * 16 + gid;
                af[mt][0] = As[cur][r][ku + tig];
                af[mt][1] = As[cur][r + 8][ku + tig];
                af[mt][2] = As[cur][r][ku + tig + 4];
                af[mt][3] = As[cur][r + 8][ku + tig + 4];
            }
#pragma unroll
            for (int nt = 0; nt < 8; nt++) {
                int c = warpN * 64 + nt * 8 + gid;
                uint32_t b0 = Bs[cur][c][ku + tig];
                uint32_t b1 = Bs[cur][c][ku + tig + 4];
                MMA_BF16(acc[0][nt], af[0], b0, b1);
                MMA_BF16(acc[1][nt], af[1], b0, b1);
            }
        }
        if (t < 15) {
            const int nxt = cur ^ 1;
            *(uint4*)&As[nxt][row][hf*8]     = pa0;
            *(uint4*)&As[nxt][row][hf*8 + 4] = pa1;
            *(uint4*)&Bs[nxt][row][hf*8]     = pb0;
            *(uint4*)&Bs[nxt][row][hf*8 + 4] = pb1;
            __syncthreads();
        }
    }

#pragma unroll
    for (int mt = 0; mt < 2; mt++) {
#pragma unroll
        for (int nt = 0; nt < 8; nt++) {
            int r = m0 + warpM * 32 + mt * 16 + gid;
            int col = n0 + warpN * 64 + nt * 8 + 2 * tig;
            float2 v0 = make_float2(acc[mt][nt][0], acc[mt][nt][1]);
            float2 v1 = make_float2(acc[mt][nt][2], acc[mt][nt][3]);
            *(float2*)(g_logits + (size_t)r * V_ + col)       = v0;
            *(float2*)(g_logits + (size_t)(r + 8) * V_ + col) = v1;
        }
    }
}

// =====================  margin select + exact rescore (+hist)  =====================
// bf16 per-logit error bound: 2^-7 * ||q||*||k||; margin = 2*bound*1.28 = 0.02
__global__ __launch_bounds__(256, 4) void k_select() {
    __shared__ float s_red[8];
    __shared__ float s_bcast;
    __shared__ int   s_cnt;
    __shared__ int   s_cand[128];
    const int row = blockIdx.x;
    const int tid = threadIdx.x;
    const int wid = tid >> 5, lane = tid & 31;
    const float4* L = (const float4*)(g_logits + (size_t)row * V_);

    float4 v[4];
    float vmax = -1e30f;
#pragma unroll
    for (int j = 0; j < 4; j++) {
        v[j] = L[tid + j * 256];
        vmax = fmaxf(vmax, fmaxf(fmaxf(v[j].x, v[j].y), fmaxf(v[j].z, v[j].w)));
    }
#pragma unroll
    for (int o = 16; o; o >>= 1) vmax = fmaxf(vmax, __shfl_xor_sync(0xffffffffu, vmax, o));
    if (lane == 0) s_red[wid] = vmax;
    if (tid == 0) s_cnt = 0;
    __syncthreads();
    if (tid == 0) {
        float m = s_red[0];
#pragma unroll
        for (int i = 1; i < 8; i++) m = fmaxf(m, s_red[i]);
        s_bcast = m;
    }
    __syncthreads();
    const float kn = __int_as_float(g_knmax_i);
    const float margin = 0.02f * g_qnorm[row] * kn + 1e-6f;
    const float thr = s_bcast - margin;

#pragma unroll
    for (int j = 0; j < 4; j++) {
        int nb = (tid + j * 256) * 4;
        float a[4] = {v[j].x, v[j].y, v[j].z, v[j].w};
#pragma unroll
        for (int c = 0; c < 4; c++) {
            if (a[c] >= thr) {
                int p = atomicAdd(&s_cnt, 1);
                if (p < 128) s_cand[p] = nb + c;
            }
        }
    }
    __syncthreads();
    int cnt = min(s_cnt, 128);

    const float* qr = g_Q + (size_t)row * C_;
    float best_v = -1e30f;
    int best_n = 1 << 30;
    for (int c = 0; c < cnt; c++) {
        int n = s_cand[c];
        const float* kr = g_kh + (size_t)n * C_;
        float p = qr[2*tid] * kr[2*tid] + qr[2*tid+1] * kr[2*tid+1];
#pragma unroll
        for (int o = 16; o; o >>= 1) p += __shfl_xor_sync(0xffffffffu, p, o);
        if (lane == 0) s_red[wid] = p;
        __syncthreads();
        if (tid == 0) {
            float sum = 0.0f;
#pragma unroll
            for (int i = 0; i < 8; i++) sum += s_red[i];
            s_bcast = sum;
        }
        __syncthreads();
        float val = s_bcast;
        if (val > best_v || (val == best_v && n < best_n)) { best_v = val; best_n = n; }
        __syncthreads();
    }
    if (tid == 0) {
        g_idx[row] = best_n;
        if (row < MFULL) atomicAdd(&g_cnt[best_n], 1);   // fused histogram
    }
}

// =====================  output kernels  =====================
__global__ void k_out(float* __restrict__ out) {
    int idx = blockIdx.x * blockDim.x + threadIdx.x;
    if (idx >= ZHAT_ELEMS) return;
    int t = idx & (T_ - 1);
    int d = (idx >> 10) & 511;
    int b = idx >> 19;
    float pos = (t + 0.5f) * ((float)Q_ / (float)T_) - 0.5f;
    pos = fminf(fmaxf(pos, 0.0f), (float)(Q_ - 1));
    int i0 = (int)pos;
    int i1 = min(i0 + 1, Q_ - 1);
    float w = pos - (float)i0;
    int n0 = g_idx[MFULL + b*Q_ + i0];
    int n1 = g_idx[MFULL + b*Q_ + i1];
    out[idx] = (1.0f - w) * g_value[(size_t)n0*C_ + d] + w * g_value[(size_t)n1*C_ + d];
}

__global__ void k_perp(float* __restrict__ out) {
    __shared__ float sm_[1024];
    int tid = threadIdx.x;
    float s = 0.0f;
    for (int j = tid; j < V_; j += 1024) {
        float p = (float)g_cnt[j] * (1.0f / 4096.0f);
        s += p * logf(p + 1e-7f);
    }
    sm_[tid] = s;
    __syncthreads();
    for (int o = 512; o; o >>= 1) {
        if (tid < o) sm_[tid] += sm_[tid + o];
        __syncthreads();
    }
    if (tid == 0) out[ZHAT_ELEMS] = expf(-sm_[0]);
}

// ---------------------------------------------------------------------------
extern "C" void kernel_launch(void* const* d_in, const int* in_sizes, int n_in,
                              void* d_out, int out_size) {
    const float* z        = (const float*)d_in[0];
    const float* codebook = (const float*)d_in[2];
    const float* Wq = (const float*)d_in[3];
    const float* bq = (const float*)d_in[4];
    const float* Wk = (const float*)d_in[5];
    const float* bk = (const float*)d_in[6];
    const float* Wv = (const float*)d_in[7];
    const float* bv = (const float*)d_in[8];
    const float* Wp = (const float*)d_in[9];
    const float* bp = (const float*)d_in[10];
    const float* gq = (const float*)d_in[11];
    const float* gk = (const float*)d_in[12];
    float* out = (float*)d_out;

    const int proj_smem = (4*AWRDS + 4*BWRDS) * 4;
    cudaFuncSetAttribute(k_proj_mma, cudaFuncAttributeMaxDynamicSharedMemorySize, proj_smem);

    k_transpose<<<dim3(16, 32, 4), dim3(32, 8)>>>(z);           // 1
    k_xp<<<16, 256>>>(Wp, bp);                                  // 2
    k_init<<<(V_ + 255)/256, 256>>>();                          // 3
    k_proj_mma<<<dim3(4, 32, 3), 256, proj_smem>>>(codebook, Wq, bq, Wk, bk, Wv, bv); // 4 (profiled)

    k_khnorm<<<V_,    512>>>(gk);
    k_qfull <<<MFULL, 512>>>(gq);
    k_qrest <<<MREST, 512>>>(gq);

    k_logits_mma<<<dim3(V_/128, MTOT/128), 256>>>();
    k_select<<<MTOT, 256>>>();

    k_out<<<(ZHAT_ELEMS + 255)/256, 256>>>(out);
    k_perp<<<1, 1024>>>(out);
}